// round 4
// baseline (speedup 1.0000x reference)
#include <cuda_runtime.h>
#include <math.h>

typedef unsigned long long ull;

// ---------------------------------------------------------------------------
// Problem constants
// ---------------------------------------------------------------------------
namespace {
constexpr int TT = 128, BB = 32;
constexpr int POS_E = 64, WORD_E = 512, POS_H = 256, WORD_H = 1024;
constexpr int POS_V = 45, WORD_V = 32000;
constexpr int NTOK = TT * BB;  // 4096

// ---------------------------------------------------------------------------
// Device scratch (static globals; no allocation allowed)
// ---------------------------------------------------------------------------
__device__ float g_p_embT[POS_E * NTOK];             // [E][tok] 1 MB
__device__ float g_w_embT[WORD_E * NTOK];            // 8 MB
__device__ float g_poutsT[POS_H * NTOK];             // pos hidden history [H][tok] 4 MB
__device__ float g_woutsT[WORD_H * NTOK];            // word L1 hidden history 16 MB
__device__ float g_wmidT[WORD_E * NTOK];             // 8 MB
__device__ float g_preT_p[4 * POS_H * NTOK];         // emb@Wih pos, [4H][tok] 16 MB
__device__ float g_preT_w0[4 * WORD_H * NTOK];       // emb@Wih word0 64 MB
// packed sequential weights
__device__ float g_Wpos[4 * POS_H * 1280];           // 5 MB
__device__ float g_Ww0[4 * WORD_H * 1280];           // 21 MB
__device__ float g_Ww1[4 * WORD_H * 2048];           // 33.5 MB
__device__ float g_bpos[4 * POS_H], g_bw0[4 * WORD_H], g_bw1[4 * WORD_H];
// recurrent state (transposed [dim][32]), ping-pong by t parity
__device__ float g_Xpos[2][1280 * BB];   // rows 0..1023: w1_h_prev, 1024..1279: p_h_prev
__device__ float g_Xw0[2][1280 * BB];    // rows 0..255: p_h_cur, 256..1279: wh0_prev
__device__ float g_Xw1[2][2048 * BB];    // rows 0..1023: wh0_cur, 1024..2047: w1_h_prev
__device__ float g_Cpos[2][POS_H * BB];
__device__ float g_Cw0[2][WORD_H * BB];
__device__ float g_Cw1[2][WORD_H * BB];
__device__ unsigned g_bar_ctr;
}  // namespace

// ---------------------------------------------------------------------------
// f32x2 packed helpers
// ---------------------------------------------------------------------------
__device__ __forceinline__ ull pack2(float lo, float hi) {
    ull r; asm("mov.b64 %0, {%1,%2};" : "=l"(r) : "f"(lo), "f"(hi)); return r;
}
__device__ __forceinline__ ull dup2(float v) { return pack2(v, v); }
__device__ __forceinline__ void fma2(ull& d, ull a, ull b) {
    asm("fma.rn.f32x2 %0, %1, %2, %0;" : "+l"(d) : "l"(a), "l"(b));
}
__device__ __forceinline__ ull add2(ull a, ull b) {
    ull r; asm("add.rn.f32x2 %0, %1, %2;" : "=l"(r) : "l"(a), "l"(b)); return r;
}
__device__ __forceinline__ void unpack2(ull v, float& lo, float& hi) {
    asm("mov.b64 {%0,%1}, %2;" : "=f"(lo), "=f"(hi) : "l"(v));
}
__device__ __forceinline__ float sigm(float x) { return 1.f / (1.f + expf(-x)); }
__device__ __forceinline__ ull shflx(ull v, int m) {
    unsigned lo = (unsigned)v, hi = (unsigned)(v >> 32);
    lo = __shfl_xor_sync(0xffffffffu, lo, m);
    hi = __shfl_xor_sync(0xffffffffu, hi, m);
    return ((ull)hi << 32) | lo;
}

// ---------------------------------------------------------------------------
// Init / gather / weight repack
// ---------------------------------------------------------------------------
__global__ void zero_init_kernel() {
    int i = blockIdx.x * blockDim.x + threadIdx.x;
    if (i < 1280 * BB) { g_Xpos[0][i] = 0.f; g_Xw0[0][i] = 0.f; }
    if (i < 2048 * BB) g_Xw1[0][i] = 0.f;
    if (i < POS_H * BB) g_Cpos[0][i] = 0.f;
    if (i < WORD_H * BB) { g_Cw0[0][i] = 0.f; g_Cw1[0][i] = 0.f; }
    if (i == 0) g_bar_ctr = 0u;
}

__global__ void gather_kernel(const int* __restrict__ pos, const int* __restrict__ word,
                              const float* __restrict__ posW, const float* __restrict__ wordW) {
    int j = blockIdx.x * blockDim.x + threadIdx.x;
    if (j < WORD_E * NTOK) {
        int d = j / NTOK, tok = j - d * NTOK;
        g_w_embT[j] = wordW[(size_t)word[tok] * WORD_E + d];
    }
    if (j < POS_E * NTOK) {
        int d = j / NTOK, tok = j - d * NTOK;
        g_p_embT[j] = posW[(size_t)pos[tok] * POS_E + d];
    }
}

// NOTE source row strides: pos_Wih rows are POS_E+WORD_H=1088 floats,
// w0_Wih rows are WORD_E+POS_H=768 floats (Round-3 bug was 1280 here).
__global__ void repack_kernel(const float* __restrict__ pWih, const float* __restrict__ pWhh,
                              const float* __restrict__ w0Wih, const float* __restrict__ w0Whh,
                              const float* __restrict__ w1Wih, const float* __restrict__ w1Whh,
                              const float* __restrict__ pbih, const float* __restrict__ pbhh,
                              const float* __restrict__ w0bih, const float* __restrict__ w0bhh,
                              const float* __restrict__ w1bih, const float* __restrict__ w1bhh) {
    int i = blockIdx.x * blockDim.x + threadIdx.x;
    const int A = 4 * POS_H * 1280;
    const int Bq = 4 * WORD_H * 1280;
    const int Cq = 4 * WORD_H * 2048;
    if (i < A) {
        int r = i / 1280, k = i - r * 1280;
        g_Wpos[i] = (k < 1024) ? pWih[(size_t)r * 1088 + 64 + k]
                               : pWhh[(size_t)r * 256 + (k - 1024)];
        return;
    }
    i -= A;
    if (i < Bq) {
        int r = i / 1280, k = i - r * 1280;
        g_Ww0[i] = (k < 256) ? w0Wih[(size_t)r * 768 + 512 + k]
                             : w0Whh[(size_t)r * 1024 + (k - 256)];
        return;
    }
    i -= Bq;
    if (i < Cq) {
        int r = i / 2048, k = i - r * 2048;
        g_Ww1[i] = (k < 1024) ? w1Wih[(size_t)r * 1024 + k]
                              : w1Whh[(size_t)r * 1024 + (k - 1024)];
        return;
    }
    i -= Cq;
    if (i < 4 * POS_H) { g_bpos[i] = pbih[i] + pbhh[i]; return; }
    i -= 4 * POS_H;
    if (i < 4 * WORD_H) { g_bw0[i] = w0bih[i] + w0bhh[i]; return; }
    i -= 4 * WORD_H;
    if (i < 4 * WORD_H) { g_bw1[i] = w1bih[i] + w1bhh[i]; }
}

// ---------------------------------------------------------------------------
// Persistent recurrence kernel: grid = 128 blocks (all resident), software
// grid barrier between cells.
// ---------------------------------------------------------------------------
__device__ __forceinline__ void grid_barrier(unsigned target) {
    __syncthreads();
    if (threadIdx.x == 0) {
        __threadfence();
        atomicAdd(&g_bar_ctr, 1u);
        while (*(volatile unsigned*)&g_bar_ctr < target) __nanosleep(64);
        __threadfence();
    }
    __syncthreads();
}

// One LSTM cell step, computed cooperatively by all 128 blocks.
//   H: hidden size, K: sequential-K (packed W cols), HPB = H/128.
//   Block owns h-range [blockIdx.x*HPB, +HPB) for all 4 gates (4*HPB rows).
//   Warp layout: lane = bpg*4 + ks (bpg: 8 batch float4 groups; ks: 4 k-slices).
template <int H, int K, int HPB>
__device__ __forceinline__ void cell_step(
    const float* __restrict__ Wpk, const float* __restrict__ bcomb,
    const float* __restrict__ preT, int tok0,
    const float* __restrict__ xT,
    const float* __restrict__ cin, float* __restrict__ cout,
    float* __restrict__ d0, float* __restrict__ d1,
    float* __restrict__ dT, float (*gbuf)[34]) {
    constexpr int ROWS = 4 * HPB;
    constexpr int RPT = ROWS / 8;   // rows per thread (per warp)
    constexpr int KPT = K / 4;      // k per k-slice
    const int tid = threadIdx.x;
    const int w = tid >> 5, lane = tid & 31;
    const int ks = lane & 3, bpg = lane >> 2;
    const int hbase = blockIdx.x * HPB;

    const float4* wp[RPT];
#pragma unroll
    for (int r = 0; r < RPT; r++) {
        int rowl = w * RPT + r;
        int g = rowl / HPB, hh = rowl - g * HPB;
        wp[r] = (const float4*)(Wpk + (size_t)(g * H + hbase + hh) * K + ks * KPT);
    }
    const float4* xp = ((const float4*)xT) + (size_t)ks * KPT * 8 + bpg;

    ull acc[RPT][2];
#pragma unroll
    for (int r = 0; r < RPT; r++) { acc[r][0] = 0ull; acc[r][1] = 0ull; }

    for (int kk = 0; kk < KPT; kk += 4) {
        float4 wv[RPT];
#pragma unroll
        for (int r = 0; r < RPT; r++) wv[r] = __ldg(&wp[r][kk >> 2]);
#pragma unroll
        for (int u = 0; u < 4; u++) {
            float4 xv = __ldcg(xp + (size_t)(kk + u) * 8);
            ull xa = pack2(xv.x, xv.y), xb = pack2(xv.z, xv.w);
#pragma unroll
            for (int r = 0; r < RPT; r++) {
                float wc = (u == 0) ? wv[r].x : (u == 1) ? wv[r].y
                          : (u == 2) ? wv[r].z : wv[r].w;
                ull wd = dup2(wc);
                fma2(acc[r][0], wd, xa);
                fma2(acc[r][1], wd, xb);
            }
        }
    }
    // reduce the 4 k-slices within each warp (lane bits 0,1)
#pragma unroll
    for (int r = 0; r < RPT; r++)
#pragma unroll
        for (int p = 0; p < 2; p++) {
            acc[r][p] = add2(acc[r][p], shflx(acc[r][p], 1));
            acc[r][p] = add2(acc[r][p], shflx(acc[r][p], 2));
        }
    if (ks == 0) {
#pragma unroll
        for (int r = 0; r < RPT; r++) {
            int rowl = w * RPT + r;
#pragma unroll
            for (int p = 0; p < 2; p++) {
                float lo, hi;
                unpack2(acc[r][p], lo, hi);
                int b0 = bpg * 4 + p * 2;
                gbuf[rowl][b0] = lo;
                gbuf[rowl][b0 + 1] = hi;
            }
        }
    }
    __syncthreads();
    // gate stage: one thread per (h, b)
    if (tid < HPB * 32) {
        int hh = tid >> 5, b = tid & 31;
        int habs = hbase + hh;
        float gi = gbuf[0 * HPB + hh][b] + bcomb[0 * H + habs];
        float gf = gbuf[1 * HPB + hh][b] + bcomb[1 * H + habs];
        float gg = gbuf[2 * HPB + hh][b] + bcomb[2 * H + habs];
        float go = gbuf[3 * HPB + hh][b] + bcomb[3 * H + habs];
        if (preT) {
            gi += __ldg(&preT[(size_t)(0 * H + habs) * NTOK + tok0 + b]);
            gf += __ldg(&preT[(size_t)(1 * H + habs) * NTOK + tok0 + b]);
            gg += __ldg(&preT[(size_t)(2 * H + habs) * NTOK + tok0 + b]);
            go += __ldg(&preT[(size_t)(3 * H + habs) * NTOK + tok0 + b]);
        }
        float i = sigm(gi), f = sigm(gf), g = tanhf(gg), o = sigm(go);
        float c2 = f * __ldcg(&cin[(size_t)habs * 32 + b]) + i * g;
        float h2 = o * tanhf(c2);
        cout[(size_t)habs * 32 + b] = c2;
        if (d0) d0[(size_t)habs * 32 + b] = h2;
        if (d1) d1[(size_t)habs * 32 + b] = h2;
        if (dT) dT[(size_t)habs * NTOK + tok0 + b] = h2;
    }
}

__global__ __launch_bounds__(256) void recurrence_kernel() {
    __shared__ float gbuf[32][34];
    unsigned ep = 0;
    const unsigned NB = gridDim.x;
    for (int t = 0; t < TT; t++) {
        const int p = t & 1, q = p ^ 1;
        const int tok0 = t * BB;
        // pos cell: x = [w1_h_prev(1024); p_h_prev(256)]
        cell_step<POS_H, 1280, 2>(g_Wpos, g_bpos, g_preT_p, tok0,
                                  g_Xpos[p], g_Cpos[p], g_Cpos[q],
                                  &g_Xpos[q][1024 * 32],   // p_h -> next pos x rows 1024..
                                  &g_Xw0[p][0],            // p_h -> current w0 x rows 0..255
                                  g_poutsT, gbuf);
        grid_barrier(++ep * NB);
        // word L0: x = [p_h_cur(256); wh0_prev(1024)]
        cell_step<WORD_H, 1280, 8>(g_Ww0, g_bw0, g_preT_w0, tok0,
                                   g_Xw0[p], g_Cw0[p], g_Cw0[q],
                                   &g_Xw1[p][0],           // wh0 -> current w1 x rows 0..1023
                                   &g_Xw0[q][256 * 32],    // wh0 -> next w0 x rows 256..
                                   nullptr, gbuf);
        grid_barrier(++ep * NB);
        // word L1: x = [wh0_cur(1024); w1_h_prev(1024)]
        cell_step<WORD_H, 2048, 8>(g_Ww1, g_bw1, nullptr, tok0,
                                   g_Xw1[p], g_Cw1[p], g_Cw1[q],
                                   &g_Xpos[q][0],          // w1_h -> next pos x rows 0..1023
                                   &g_Xw1[q][1024 * 32],   // w1_h -> next w1 x rows 1024..
                                   g_woutsT, gbuf);
        grid_barrier(++ep * NB);
    }
}

// ---------------------------------------------------------------------------
// f32x2 GEMM: C[m,n] = sum_k AT[k,m]*W[n,k] + bias[n]; writes C and/or CT.
// ---------------------------------------------------------------------------
__global__ __launch_bounds__(256, 2) void gemm_t_kernel(
    const float* __restrict__ AT, int M,
    const float* __restrict__ W, int ldw, const float* __restrict__ bias,
    float* __restrict__ C, float* __restrict__ CT, int N, int K) {
    __shared__ float As[32][128];
    __shared__ float Ws[32][132];
    const int tid = threadIdx.x;
    const int rt = tid & 15;
    const int ct = tid >> 4;
    const int rBase = blockIdx.y * 128, cBase = blockIdx.x * 128;

    ull acc[8][4];
#pragma unroll
    for (int jj = 0; jj < 8; jj++)
#pragma unroll
        for (int p = 0; p < 4; p++) acc[jj][p] = 0ull;

    for (int kb = 0; kb < K; kb += 32) {
#pragma unroll
        for (int it = 0; it < 4; it++) {
            int flat = tid + it * 256;
            int k = flat >> 5, m4 = flat & 31;
            float4 v = *(const float4*)&AT[(size_t)(kb + k) * M + rBase + m4 * 4];
            *(float4*)&As[k][m4 * 4] = v;
        }
#pragma unroll
        for (int it = 0; it < 4; it++) {
            int flat = tid + it * 256;
            int n = flat >> 3, k4 = flat & 7;
            float4 v = *(const float4*)&W[(size_t)(cBase + n) * ldw + kb + k4 * 4];
            Ws[k4 * 4 + 0][n] = v.x;
            Ws[k4 * 4 + 1][n] = v.y;
            Ws[k4 * 4 + 2][n] = v.z;
            Ws[k4 * 4 + 3][n] = v.w;
        }
        __syncthreads();
#pragma unroll
        for (int k = 0; k < 32; k++) {
            ull xd[8];
#pragma unroll
            for (int jj = 0; jj < 8; jj++) xd[jj] = dup2(As[k][rt + 16 * jj]);
            const ulonglong2* wpp = (const ulonglong2*)&Ws[k][ct * 8];
            ulonglong2 wa = wpp[0];
            ulonglong2 wb = wpp[1];
#pragma unroll
            for (int jj = 0; jj < 8; jj++) {
                fma2(acc[jj][0], xd[jj], wa.x);
                fma2(acc[jj][1], xd[jj], wa.y);
                fma2(acc[jj][2], xd[jj], wb.x);
                fma2(acc[jj][3], xd[jj], wb.y);
            }
        }
        __syncthreads();
    }
    float bcol[8];
#pragma unroll
    for (int qq = 0; qq < 8; qq++) bcol[qq] = bias ? bias[cBase + ct * 8 + qq] : 0.f;
#pragma unroll
    for (int jj = 0; jj < 8; jj++) {
        int m = rBase + rt + 16 * jj;
        float v[8];
#pragma unroll
        for (int p = 0; p < 4; p++) unpack2(acc[jj][p], v[2 * p], v[2 * p + 1]);
#pragma unroll
        for (int qq = 0; qq < 8; qq++) v[qq] += bcol[qq];
        if (C) {
            float4* dst = (float4*)&C[(size_t)m * N + cBase + ct * 8];
            dst[0] = make_float4(v[0], v[1], v[2], v[3]);
            dst[1] = make_float4(v[4], v[5], v[6], v[7]);
        }
        if (CT) {
#pragma unroll
            for (int qq = 0; qq < 8; qq++)
                CT[(size_t)(cBase + ct * 8 + qq) * M + m] = v[qq];
        }
    }
}

// ---------------------------------------------------------------------------
// pos projection + log-softmax from transposed hidden history.
// One block per timestep (32 tokens x 45 vocab).
// ---------------------------------------------------------------------------
__global__ void pos_projT_kernel(const float* __restrict__ Wp, const float* __restrict__ bp,
                                 float* __restrict__ out) {
    __shared__ float xs[POS_H][32];
    __shared__ float lg[POS_V][33];
    __shared__ float lsb[32];
    const int t = blockIdx.x;
    const int tok0 = t * 32;
    const int tid = threadIdx.x;
    const int b = tid & 31, vg = tid >> 5;
    for (int i = tid; i < POS_H * 32; i += 256) {
        int k = i >> 5, bb = i & 31;
        xs[k][bb] = g_poutsT[(size_t)k * NTOK + tok0 + bb];
    }
    __syncthreads();
    for (int v = vg; v < POS_V; v += 8) {
        float s = bp[v];
        const float* wv = Wp + (size_t)v * POS_H;
        for (int k = 0; k < POS_H; k++) s = fmaf(xs[k][b], wv[k], s);
        lg[v][b] = s;
    }
    __syncthreads();
    if (tid < 32) {
        float m = -INFINITY;
        for (int v = 0; v < POS_V; v++) m = fmaxf(m, lg[v][tid]);
        float e = 0.f;
        for (int v = 0; v < POS_V; v++) e += expf(lg[v][tid] - m);
        lsb[tid] = m + logf(e);
    }
    __syncthreads();
    float ls = lsb[b];
    for (int v = vg; v < POS_V; v += 8)
        out[(size_t)(tok0 + b) * POS_V + v] = lg[v][b] - ls;
}

// ---------------------------------------------------------------------------
// word log-softmax in place over 32000 (one block per row)
// ---------------------------------------------------------------------------
__global__ void word_softmax_kernel(float* __restrict__ logits) {
    __shared__ float red[8];
    const int row = blockIdx.x;
    float* p = logits + (size_t)row * WORD_V;
    const int tid = threadIdx.x;
    float m = -INFINITY;
    for (int i = tid; i < WORD_V; i += 256) m = fmaxf(m, p[i]);
#pragma unroll
    for (int o = 16; o; o >>= 1) m = fmaxf(m, __shfl_xor_sync(0xffffffffu, m, o));
    if ((tid & 31) == 0) red[tid >> 5] = m;
    __syncthreads();
    float M = red[0];
#pragma unroll
    for (int w = 1; w < 8; w++) M = fmaxf(M, red[w]);
    __syncthreads();
    float s = 0.f;
    for (int i = tid; i < WORD_V; i += 256) s += expf(p[i] - M);
#pragma unroll
    for (int o = 16; o; o >>= 1) s += __shfl_xor_sync(0xffffffffu, s, o);
    if ((tid & 31) == 0) red[tid >> 5] = s;
    __syncthreads();
    float S = 0.f;
#pragma unroll
    for (int w = 0; w < 8; w++) S += red[w];
    float ls = M + logf(S);
    for (int i = tid; i < WORD_V; i += 256) p[i] -= ls;
}

// ---------------------------------------------------------------------------
// Host side
// ---------------------------------------------------------------------------
extern "C" void kernel_launch(void* const* d_in, const int* in_sizes, int n_in,
                              void* d_out, int out_size) {
    (void)in_sizes; (void)n_in; (void)out_size;
    const int*   pos        = (const int*)d_in[0];
    const int*   word       = (const int*)d_in[1];
    const float* pos_emb_W  = (const float*)d_in[2];
    const float* word_emb_W = (const float*)d_in[3];
    const float* pos_Wih    = (const float*)d_in[4];
    const float* pos_Whh    = (const float*)d_in[5];
    const float* pos_bih    = (const float*)d_in[6];
    const float* pos_bhh    = (const float*)d_in[7];
    const float* w0_Wih     = (const float*)d_in[8];
    const float* w0_Whh     = (const float*)d_in[9];
    const float* w0_bih     = (const float*)d_in[10];
    const float* w0_bhh     = (const float*)d_in[11];
    const float* w1_Wih     = (const float*)d_in[12];
    const float* w1_Whh     = (const float*)d_in[13];
    const float* w1_bih     = (const float*)d_in[14];
    const float* w1_bhh     = (const float*)d_in[15];
    const float* pos_proj_W = (const float*)d_in[16];
    const float* pos_proj_b = (const float*)d_in[17];
    const float* wp1_W      = (const float*)d_in[18];
    const float* wp1_b      = (const float*)d_in[19];
    const float* wp2_b      = (const float*)d_in[20];
    float* out = (float*)d_out;

    float *p_embT, *w_embT, *woutsT, *wmidT, *preT_p, *preT_w0;
    cudaGetSymbolAddress((void**)&p_embT, g_p_embT);
    cudaGetSymbolAddress((void**)&w_embT, g_w_embT);
    cudaGetSymbolAddress((void**)&woutsT, g_woutsT);
    cudaGetSymbolAddress((void**)&wmidT, g_wmidT);
    cudaGetSymbolAddress((void**)&preT_p, g_preT_p);
    cudaGetSymbolAddress((void**)&preT_w0, g_preT_w0);

    zero_init_kernel<<<(2048 * BB + 255) / 256, 256>>>();
    gather_kernel<<<(WORD_E * NTOK + 255) / 256, 256>>>(pos, word, pos_emb_W, word_emb_W);

    {
        const int total = 4 * POS_H * 1280 + 4 * WORD_H * 1280 + 4 * WORD_H * 2048 +
                          4 * POS_H + 2 * (4 * WORD_H);
        repack_kernel<<<(total + 255) / 256, 256>>>(
            pos_Wih, pos_Whh, w0_Wih, w0_Whh, w1_Wih, w1_Whh,
            pos_bih, pos_bhh, w0_bih, w0_bhh, w1_bih, w1_bhh);
    }

    // precompute emb @ Wih_emb-part for all timesteps (transposed outputs)
    gemm_t_kernel<<<dim3(4 * POS_H / 128, NTOK / 128), 256>>>(
        p_embT, NTOK, pos_Wih, POS_E + WORD_H, nullptr, nullptr, preT_p, 4 * POS_H, POS_E);
    gemm_t_kernel<<<dim3(4 * WORD_H / 128, NTOK / 128), 256>>>(
        w_embT, NTOK, w0_Wih, WORD_E + POS_H, nullptr, nullptr, preT_w0, 4 * WORD_H, WORD_E);

    // the whole 128-step recurrence in ONE persistent kernel
    recurrence_kernel<<<128, 256>>>();

    // pos projection + log-softmax
    pos_projT_kernel<<<TT, 256>>>(pos_proj_W, pos_proj_b, out);

    // word head
    gemm_t_kernel<<<dim3(WORD_E / 128, NTOK / 128), 256>>>(
        woutsT, NTOK, wp1_W, WORD_H, wp1_b, nullptr, wmidT, WORD_E, WORD_H);
    float* wlp = out + (size_t)NTOK * POS_V;
    gemm_t_kernel<<<dim3(WORD_V / 128, NTOK / 128), 256>>>(
        wmidT, NTOK, word_emb_W, WORD_E, wp2_b, wlp, nullptr, WORD_V, WORD_E);
    word_softmax_kernel<<<NTOK, 256>>>(wlp);
}

// round 5
// speedup vs baseline: 2.0900x; 2.0900x over previous
#include <cuda_runtime.h>
#include <math.h>

typedef unsigned long long ull;

// ---------------------------------------------------------------------------
// Problem constants
// ---------------------------------------------------------------------------
namespace {
constexpr int TT = 128, BB = 32;
constexpr int POS_E = 64, WORD_E = 512, POS_H = 256, WORD_H = 1024;
constexpr int POS_V = 45, WORD_V = 32000;
constexpr int NTOK = TT * BB;      // 4096
constexpr int NTOKP = NTOK + 32;   // history col 0 = zeros (t = -1 slot)

// ---------------------------------------------------------------------------
// Device scratch (static globals; no allocation allowed)
// ---------------------------------------------------------------------------
__device__ float g_p_embT[POS_E * NTOK];             // [E][tok]
__device__ float g_w_embT[WORD_E * NTOK];
__device__ float g_poutsT[POS_H * NTOKP];            // histories [H][NTOKP], slot t+1
__device__ float g_wh0T[WORD_H * NTOKP];
__device__ float g_woutsT[WORD_H * NTOKP];
__device__ float g_wmidT[WORD_E * NTOK];
__device__ float g_preT_p[4 * POS_H * NTOK];         // emb@Wih pos, [4H][tok]
__device__ float g_preT_w0[4 * WORD_H * NTOK];
// packed sequential weights, k-major per block: [blk][K][ROWS]
__device__ float g_Wpos[4 * POS_H * 1280];           // [128][1280][8]
__device__ float g_Ww0[4 * WORD_H * 1280];           // [128][1280][32]
__device__ float g_Ww1[4 * WORD_H * 2048];           // [128][2048][32]
__device__ float g_bpos[4 * POS_H], g_bw0[4 * WORD_H], g_bw1[4 * WORD_H];
// cell state ping-pong (each [H][32]; block-private rows)
__device__ float g_Cpos[2][POS_H * BB];
__device__ float g_Cw0[2][WORD_H * BB];
__device__ float g_Cw1[2][WORD_H * BB];
__device__ unsigned g_bar_ctr;
}  // namespace

// ---------------------------------------------------------------------------
// f32x2 packed helpers
// ---------------------------------------------------------------------------
__device__ __forceinline__ ull pack2(float lo, float hi) {
    ull r; asm("mov.b64 %0, {%1,%2};" : "=l"(r) : "f"(lo), "f"(hi)); return r;
}
__device__ __forceinline__ ull dup2(float v) { return pack2(v, v); }
__device__ __forceinline__ void fma2(ull& d, ull a, ull b) {
    asm("fma.rn.f32x2 %0, %1, %2, %0;" : "+l"(d) : "l"(a), "l"(b));
}
__device__ __forceinline__ void unpack2(ull v, float& lo, float& hi) {
    asm("mov.b64 {%0,%1}, %2;" : "=f"(lo), "=f"(hi) : "l"(v));
}
__device__ __forceinline__ float sigm(float x) { return 1.f / (1.f + expf(-x)); }

// ---------------------------------------------------------------------------
// Init / gather / weight repack
// ---------------------------------------------------------------------------
__global__ void zero_init_kernel() {
    int i = blockIdx.x * blockDim.x + threadIdx.x;
    if (i < POS_H * BB) {
        g_poutsT[(size_t)(i >> 5) * NTOKP + (i & 31)] = 0.f;
        g_Cpos[0][i] = 0.f;
    }
    if (i < WORD_H * BB) {
        int r = i >> 5, b = i & 31;
        g_wh0T[(size_t)r * NTOKP + b] = 0.f;
        g_woutsT[(size_t)r * NTOKP + b] = 0.f;
        g_Cw0[0][i] = 0.f;
        g_Cw1[0][i] = 0.f;
    }
    if (i == 0) g_bar_ctr = 0u;
}

__global__ void gather_kernel(const int* __restrict__ pos, const int* __restrict__ word,
                              const float* __restrict__ posW, const float* __restrict__ wordW) {
    int j = blockIdx.x * blockDim.x + threadIdx.x;
    if (j < WORD_E * NTOK) {
        int d = j / NTOK, tok = j - d * NTOK;
        g_w_embT[j] = wordW[(size_t)word[tok] * WORD_E + d];
    }
    if (j < POS_E * NTOK) {
        int d = j / NTOK, tok = j - d * NTOK;
        g_p_embT[j] = posW[(size_t)pos[tok] * POS_E + d];
    }
}

// Repack into k-major per-block layout.
//   pos:  [blk][k][rowl]  rowl = g*2 + hh, habs = blk*2+hh, R = g*256+habs
//   word: [blk][k][rowl]  rowl = g*8 + hh, habs = blk*8+hh, R = g*1024+habs
// Source row strides: pos_Wih 1088, w0_Wih 768, w1_Wih 1024 (all *_Whh per spec).
__global__ void repack_kernel(const float* __restrict__ pWih, const float* __restrict__ pWhh,
                              const float* __restrict__ w0Wih, const float* __restrict__ w0Whh,
                              const float* __restrict__ w1Wih, const float* __restrict__ w1Whh,
                              const float* __restrict__ pbih, const float* __restrict__ pbhh,
                              const float* __restrict__ w0bih, const float* __restrict__ w0bhh,
                              const float* __restrict__ w1bih, const float* __restrict__ w1bhh) {
    int i = blockIdx.x * blockDim.x + threadIdx.x;
    const int A = 4 * POS_H * 1280;
    const int Bq = 4 * WORD_H * 1280;
    const int Cq = 4 * WORD_H * 2048;
    if (i < A) {
        int blk = i / (1280 * 8), rem = i - blk * (1280 * 8);
        int k = rem >> 3, rowl = rem & 7;
        int g = rowl >> 1, hh = rowl & 1;
        int R = g * POS_H + blk * 2 + hh;
        g_Wpos[i] = (k < 1024) ? pWih[(size_t)R * 1088 + 64 + k]
                               : pWhh[(size_t)R * 256 + (k - 1024)];
        return;
    }
    i -= A;
    if (i < Bq) {
        int blk = i / (1280 * 32), rem = i - blk * (1280 * 32);
        int k = rem >> 5, rowl = rem & 31;
        int g = rowl >> 3, hh = rowl & 7;
        int R = g * WORD_H + blk * 8 + hh;
        g_Ww0[i] = (k < 256) ? w0Wih[(size_t)R * 768 + 512 + k]
                             : w0Whh[(size_t)R * 1024 + (k - 256)];
        return;
    }
    i -= Bq;
    if (i < Cq) {
        int blk = i / (2048 * 32), rem = i - blk * (2048 * 32);
        int k = rem >> 5, rowl = rem & 31;
        int g = rowl >> 3, hh = rowl & 7;
        int R = g * WORD_H + blk * 8 + hh;
        g_Ww1[i] = (k < 1024) ? w1Wih[(size_t)R * 1024 + k]
                              : w1Whh[(size_t)R * 1024 + (k - 1024)];
        return;
    }
    i -= Cq;
    if (i < 4 * POS_H) { g_bpos[i] = pbih[i] + pbhh[i]; return; }
    i -= 4 * POS_H;
    if (i < 4 * WORD_H) { g_bw0[i] = w0bih[i] + w0bhh[i]; return; }
    i -= 4 * WORD_H;
    if (i < 4 * WORD_H) { g_bw1[i] = w1bih[i] + w1bhh[i]; }
}

// ---------------------------------------------------------------------------
// Persistent recurrence kernel (128 blocks x 256 threads, all resident).
// ---------------------------------------------------------------------------
struct SmemCell {
    float xs[64][32];        // [k][batch]  8 KB
    float ws[64][32];        // [k][row]    8 KB (pos uses cols 0..7)
    float red[8][32][32];    // k-slice partials  32 KB
};

__device__ __forceinline__ void grid_barrier(unsigned target) {
    __syncthreads();
    if (threadIdx.x == 0) {
        __threadfence();
        atomicAdd(&g_bar_ctr, 1u);
        while (*(volatile unsigned*)&g_bar_ctr < target) __nanosleep(64);
        __threadfence();
    }
    __syncthreads();
}

// Word-size LSTM cell (H=1024, HPB=8, ROWS=32). K chunked by 64, smem-staged,
// register double-buffered. Warp w = k-slice (8 k per chunk); lane: rowg(8) x bg(4).
template <int K>
__device__ __forceinline__ void cell_word(
    SmemCell* sm, const float* __restrict__ Wblk,
    const float* __restrict__ bcomb,
    const float* __restrict__ preT, int tok0,
    const float* __restrict__ x1, int K1, const float* __restrict__ x2,
    const float* __restrict__ cin, float* __restrict__ cout,
    float* __restrict__ hcol) {
    constexpr int NC = K / 64;
    const int tid = threadIdx.x;
    const int w = tid >> 5, lane = tid & 31;
    const int rowg = lane >> 2;   // rows rowg*4..+3
    const int bg = lane & 3;      // batch bg*8..+7

    ull acc[4][4];
#pragma unroll
    for (int r = 0; r < 4; r++)
#pragma unroll
        for (int j = 0; j < 4; j++) acc[r][j] = 0ull;

    float4 px[2], pw[2];
#pragma unroll
    for (int it = 0; it < 2; it++) {   // prefetch chunk 0 (kb=0 < K1 always)
        int f = tid + it * 256;
        px[it] = *(const float4*)(x1 + (size_t)(f >> 3) * NTOKP + (f & 7) * 4);
        pw[it] = *(const float4*)(Wblk + (size_t)(f >> 3) * 32 + (f & 7) * 4);
    }

    for (int c = 0; c < NC; c++) {
        __syncthreads();
#pragma unroll
        for (int it = 0; it < 2; it++) {
            int f = tid + it * 256;
            *(float4*)&sm->xs[f >> 3][(f & 7) * 4] = px[it];
            *(float4*)&sm->ws[f >> 3][(f & 7) * 4] = pw[it];
        }
        __syncthreads();
        if (c + 1 < NC) {
            int kb = (c + 1) * 64;
            const float* xsrc = (kb < K1) ? x1 + (size_t)kb * NTOKP
                                          : x2 + (size_t)(kb - K1) * NTOKP;
            const float* wsrc = Wblk + (size_t)kb * 32;
#pragma unroll
            for (int it = 0; it < 2; it++) {
                int f = tid + it * 256;
                px[it] = *(const float4*)(xsrc + (size_t)(f >> 3) * NTOKP + (f & 7) * 4);
                pw[it] = *(const float4*)(wsrc + (size_t)(f >> 3) * 32 + (f & 7) * 4);
            }
        }
#pragma unroll
        for (int kk = 0; kk < 8; kk++) {
            int k = w * 8 + kk;
            const ulonglong2* xp = (const ulonglong2*)&sm->xs[k][bg * 8];
            ulonglong2 xv0 = xp[0], xv1 = xp[1];
            const float* wr = &sm->ws[k][rowg * 4];
#pragma unroll
            for (int r = 0; r < 4; r++) {
                ull wd = dup2(wr[r]);
                fma2(acc[r][0], wd, xv0.x);
                fma2(acc[r][1], wd, xv0.y);
                fma2(acc[r][2], wd, xv1.x);
                fma2(acc[r][3], wd, xv1.y);
            }
        }
    }
    // dump k-slice partials
#pragma unroll
    for (int r = 0; r < 4; r++) {
        int row = rowg * 4 + r;
#pragma unroll
        for (int j = 0; j < 4; j += 2) {
            float a0, a1, a2, a3;
            unpack2(acc[r][j], a0, a1);
            unpack2(acc[r][j + 1], a2, a3);
            *(float4*)&sm->red[w][row][bg * 8 + j * 2] = make_float4(a0, a1, a2, a3);
        }
    }
    __syncthreads();
    // gate stage: 256 threads = 8 h x 32 b
    {
        int hh = tid >> 5, b = tid & 31;
        int habs = blockIdx.x * 8 + hh;
        float gs[4];
#pragma unroll
        for (int g = 0; g < 4; g++) {
            float s = bcomb[g * WORD_H + habs];
#pragma unroll
            for (int ww = 0; ww < 8; ww++) s += sm->red[ww][g * 8 + hh][b];
            if (preT) s += preT[(size_t)(g * WORD_H + habs) * NTOK + tok0 + b];
            gs[g] = s;
        }
        float i = sigm(gs[0]), f = sigm(gs[1]), g = tanhf(gs[2]), o = sigm(gs[3]);
        float c2 = f * cin[habs * 32 + b] + i * g;
        float h2 = o * tanhf(c2);
        cout[habs * 32 + b] = c2;
        hcol[(size_t)habs * NTOKP + b] = h2;
    }
}

// Pos cell (H=256, HPB=2, ROWS=8, K=1280). 4 k-slices of 64 threads each:
// sub: rowl(8) x bg(8, 4 batch each).
__device__ __forceinline__ void cell_pos(
    SmemCell* sm, const float* __restrict__ Wblk,
    const float* __restrict__ bcomb,
    const float* __restrict__ preT, int tok0,
    const float* __restrict__ x1 /*1024 rows*/, const float* __restrict__ x2 /*256*/,
    const float* __restrict__ cin, float* __restrict__ cout,
    float* __restrict__ hcol) {
    constexpr int K = 1280, NC = K / 64, K1 = 1024;
    const int tid = threadIdx.x;
    const int ksl = tid >> 6;
    const int sub = tid & 63;
    const int rowl = sub >> 3;   // 0..7
    const int bg = sub & 7;      // batch bg*4..+3

    ull acc0 = 0ull, acc1 = 0ull;
    float4 px[2], pw;
#pragma unroll
    for (int it = 0; it < 2; it++) {
        int f = tid + it * 256;
        px[it] = *(const float4*)(x1 + (size_t)(f >> 3) * NTOKP + (f & 7) * 4);
    }
    if (tid < 128)
        pw = *(const float4*)(Wblk + (size_t)(tid >> 1) * 8 + (tid & 1) * 4);

    for (int c = 0; c < NC; c++) {
        __syncthreads();
#pragma unroll
        for (int it = 0; it < 2; it++) {
            int f = tid + it * 256;
            *(float4*)&sm->xs[f >> 3][(f & 7) * 4] = px[it];
        }
        if (tid < 128)
            *(float4*)&sm->ws[tid >> 1][(tid & 1) * 4] = pw;
        __syncthreads();
        if (c + 1 < NC) {
            int kb = (c + 1) * 64;
            const float* xsrc = (kb < K1) ? x1 + (size_t)kb * NTOKP
                                          : x2 + (size_t)(kb - K1) * NTOKP;
#pragma unroll
            for (int it = 0; it < 2; it++) {
                int f = tid + it * 256;
                px[it] = *(const float4*)(xsrc + (size_t)(f >> 3) * NTOKP + (f & 7) * 4);
            }
            if (tid < 128)
                pw = *(const float4*)(Wblk + (size_t)(kb + (tid >> 1)) * 8 + (tid & 1) * 4);
        }
#pragma unroll
        for (int kk = 0; kk < 16; kk++) {
            int k = ksl * 16 + kk;
            ulonglong2 xv = *(const ulonglong2*)&sm->xs[k][bg * 4];
            ull wd = dup2(sm->ws[k][rowl]);
            fma2(acc0, wd, xv.x);
            fma2(acc1, wd, xv.y);
        }
    }
    {
        float a0, a1, a2, a3;
        unpack2(acc0, a0, a1);
        unpack2(acc1, a2, a3);
        *(float4*)&sm->red[ksl][rowl][bg * 4] = make_float4(a0, a1, a2, a3);
    }
    __syncthreads();
    if (tid < 64) {
        int hh = tid >> 5, b = tid & 31;
        int habs = blockIdx.x * 2 + hh;
        float gs[4];
#pragma unroll
        for (int g = 0; g < 4; g++) {
            float s = bcomb[g * POS_H + habs];
#pragma unroll
            for (int s4 = 0; s4 < 4; s4++) s += sm->red[s4][g * 2 + hh][b];
            s += preT[(size_t)(g * POS_H + habs) * NTOK + tok0 + b];
            gs[g] = s;
        }
        float i = sigm(gs[0]), f = sigm(gs[1]), g = tanhf(gs[2]), o = sigm(gs[3]);
        float c2 = f * cin[habs * 32 + b] + i * g;
        float h2 = o * tanhf(c2);
        cout[habs * 32 + b] = c2;
        hcol[(size_t)habs * NTOKP + b] = h2;
    }
}

__global__ __launch_bounds__(256) void recurrence_kernel() {
    __shared__ SmemCell sm;
    unsigned ep = 0;
    const unsigned NB = gridDim.x;
    const int blk = blockIdx.x;
    const float* WposB = g_Wpos + (size_t)blk * 1280 * 8;
    const float* Ww0B  = g_Ww0 + (size_t)blk * 1280 * 32;
    const float* Ww1B  = g_Ww1 + (size_t)blk * 2048 * 32;
    for (int t = 0; t < TT; t++) {
        const int p = t & 1, q = p ^ 1;
        const int tok0 = t * BB;
        // pos: x = [w1_h(t-1); p_h(t-1)]
        cell_pos(&sm, WposB, g_bpos, g_preT_p, tok0,
                 g_woutsT + (size_t)t * 32, g_poutsT + (size_t)t * 32,
                 g_Cpos[p], g_Cpos[q], g_poutsT + (size_t)(t + 1) * 32);
        grid_barrier(++ep * NB);
        // w0: x = [p_h(t); wh0(t-1)]
        cell_word<1280>(&sm, Ww0B, g_bw0, g_preT_w0, tok0,
                        g_poutsT + (size_t)(t + 1) * 32, 256,
                        g_wh0T + (size_t)t * 32,
                        g_Cw0[p], g_Cw0[q], g_wh0T + (size_t)(t + 1) * 32);
        grid_barrier(++ep * NB);
        // w1: x = [wh0(t); w1_h(t-1)]
        cell_word<2048>(&sm, Ww1B, g_bw1, nullptr, tok0,
                        g_wh0T + (size_t)(t + 1) * 32, 1024,
                        g_woutsT + (size_t)t * 32,
                        g_Cw1[p], g_Cw1[q], g_woutsT + (size_t)(t + 1) * 32);
        grid_barrier(++ep * NB);
    }
}

// ---------------------------------------------------------------------------
// f32x2 GEMM: C[m,n] = sum_k AT[k,m]*W[n,k] + bias[n]; AT row stride = lda.
// ---------------------------------------------------------------------------
__global__ __launch_bounds__(256, 2) void gemm_t_kernel(
    const float* __restrict__ AT, int M, int lda,
    const float* __restrict__ W, int ldw, const float* __restrict__ bias,
    float* __restrict__ C, float* __restrict__ CT, int N, int K) {
    __shared__ float As[32][128];
    __shared__ float Ws[32][132];
    const int tid = threadIdx.x;
    const int rt = tid & 15;
    const int ct = tid >> 4;
    const int rBase = blockIdx.y * 128, cBase = blockIdx.x * 128;

    ull acc[8][4];
#pragma unroll
    for (int jj = 0; jj < 8; jj++)
#pragma unroll
        for (int p = 0; p < 4; p++) acc[jj][p] = 0ull;

    for (int kb = 0; kb < K; kb += 32) {
#pragma unroll
        for (int it = 0; it < 4; it++) {
            int flat = tid + it * 256;
            int k = flat >> 5, m4 = flat & 31;
            float4 v = *(const float4*)&AT[(size_t)(kb + k) * lda + rBase + m4 * 4];
            *(float4*)&As[k][m4 * 4] = v;
        }
#pragma unroll
        for (int it = 0; it < 4; it++) {
            int flat = tid + it * 256;
            int n = flat >> 3, k4 = flat & 7;
            float4 v = *(const float4*)&W[(size_t)(cBase + n) * ldw + kb + k4 * 4];
            Ws[k4 * 4 + 0][n] = v.x;
            Ws[k4 * 4 + 1][n] = v.y;
            Ws[k4 * 4 + 2][n] = v.z;
            Ws[k4 * 4 + 3][n] = v.w;
        }
        __syncthreads();
#pragma unroll
        for (int k = 0; k < 32; k++) {
            ull xd[8];
#pragma unroll
            for (int jj = 0; jj < 8; jj++) xd[jj] = dup2(As[k][rt + 16 * jj]);
            const ulonglong2* wpp = (const ulonglong2*)&Ws[k][ct * 8];
            ulonglong2 wa = wpp[0];
            ulonglong2 wb = wpp[1];
#pragma unroll
            for (int jj = 0; jj < 8; jj++) {
                fma2(acc[jj][0], xd[jj], wa.x);
                fma2(acc[jj][1], xd[jj], wa.y);
                fma2(acc[jj][2], xd[jj], wb.x);
                fma2(acc[jj][3], xd[jj], wb.y);
            }
        }
        __syncthreads();
    }
    float bcol[8];
#pragma unroll
    for (int qq = 0; qq < 8; qq++) bcol[qq] = bias ? bias[cBase + ct * 8 + qq] : 0.f;
#pragma unroll
    for (int jj = 0; jj < 8; jj++) {
        int m = rBase + rt + 16 * jj;
        float v[8];
#pragma unroll
        for (int p = 0; p < 4; p++) unpack2(acc[jj][p], v[2 * p], v[2 * p + 1]);
#pragma unroll
        for (int qq = 0; qq < 8; qq++) v[qq] += bcol[qq];
        if (C) {
            float4* dst = (float4*)&C[(size_t)m * N + cBase + ct * 8];
            dst[0] = make_float4(v[0], v[1], v[2], v[3]);
            dst[1] = make_float4(v[4], v[5], v[6], v[7]);
        }
        if (CT) {
#pragma unroll
            for (int qq = 0; qq < 8; qq++)
                CT[(size_t)(cBase + ct * 8 + qq) * M + m] = v[qq];
        }
    }
}

// ---------------------------------------------------------------------------
// pos projection + log-softmax (one block per timestep)
// ---------------------------------------------------------------------------
__global__ void pos_projT_kernel(const float* __restrict__ Wp, const float* __restrict__ bp,
                                 float* __restrict__ out) {
    __shared__ float xs[POS_H][32];
    __shared__ float lg[POS_V][33];
    __shared__ float lsb[32];
    const int t = blockIdx.x;
    const int tok0 = t * 32;
    const int tid = threadIdx.x;
    const int b = tid & 31, vg = tid >> 5;
    for (int i = tid; i < POS_H * 32; i += 256) {
        int k = i >> 5, bb = i & 31;
        xs[k][bb] = g_poutsT[(size_t)k * NTOKP + 32 + tok0 + bb];
    }
    __syncthreads();
    for (int v = vg; v < POS_V; v += 8) {
        float s = bp[v];
        const float* wv = Wp + (size_t)v * POS_H;
        for (int k = 0; k < POS_H; k++) s = fmaf(xs[k][b], wv[k], s);
        lg[v][b] = s;
    }
    __syncthreads();
    if (tid < 32) {
        float m = -INFINITY;
        for (int v = 0; v < POS_V; v++) m = fmaxf(m, lg[v][tid]);
        float e = 0.f;
        for (int v = 0; v < POS_V; v++) e += expf(lg[v][tid] - m);
        lsb[tid] = m + logf(e);
    }
    __syncthreads();
    float ls = lsb[b];
    for (int v = vg; v < POS_V; v += 8)
        out[(size_t)(tok0 + b) * POS_V + v] = lg[v][b] - ls;
}

// ---------------------------------------------------------------------------
// word log-softmax in place over 32000 (one block per row)
// ---------------------------------------------------------------------------
__global__ void word_softmax_kernel(float* __restrict__ logits) {
    __shared__ float red[8];
    const int row = blockIdx.x;
    float* p = logits + (size_t)row * WORD_V;
    const int tid = threadIdx.x;
    float m = -INFINITY;
    for (int i = tid; i < WORD_V; i += 256) m = fmaxf(m, p[i]);
#pragma unroll
    for (int o = 16; o; o >>= 1) m = fmaxf(m, __shfl_xor_sync(0xffffffffu, m, o));
    if ((tid & 31) == 0) red[tid >> 5] = m;
    __syncthreads();
    float M = red[0];
#pragma unroll
    for (int w = 1; w < 8; w++) M = fmaxf(M, red[w]);
    __syncthreads();
    float s = 0.f;
    for (int i = tid; i < WORD_V; i += 256) s += expf(p[i] - M);
#pragma unroll
    for (int o = 16; o; o >>= 1) s += __shfl_xor_sync(0xffffffffu, s, o);
    if ((tid & 31) == 0) red[tid >> 5] = s;
    __syncthreads();
    float S = 0.f;
#pragma unroll
    for (int w = 0; w < 8; w++) S += red[w];
    float ls = M + logf(S);
    for (int i = tid; i < WORD_V; i += 256) p[i] -= ls;
}

// ---------------------------------------------------------------------------
// Host side
// ---------------------------------------------------------------------------
extern "C" void kernel_launch(void* const* d_in, const int* in_sizes, int n_in,
                              void* d_out, int out_size) {
    (void)in_sizes; (void)n_in; (void)out_size;
    const int*   pos        = (const int*)d_in[0];
    const int*   word       = (const int*)d_in[1];
    const float* pos_emb_W  = (const float*)d_in[2];
    const float* word_emb_W = (const float*)d_in[3];
    const float* pos_Wih    = (const float*)d_in[4];
    const float* pos_Whh    = (const float*)d_in[5];
    const float* pos_bih    = (const float*)d_in[6];
    const float* pos_bhh    = (const float*)d_in[7];
    const float* w0_Wih     = (const float*)d_in[8];
    const float* w0_Whh     = (const float*)d_in[9];
    const float* w0_bih     = (const float*)d_in[10];
    const float* w0_bhh     = (const float*)d_in[11];
    const float* w1_Wih     = (const float*)d_in[12];
    const float* w1_Whh     = (const float*)d_in[13];
    const float* w1_bih     = (const float*)d_in[14];
    const float* w1_bhh     = (const float*)d_in[15];
    const float* pos_proj_W = (const float*)d_in[16];
    const float* pos_proj_b = (const float*)d_in[17];
    const float* wp1_W      = (const float*)d_in[18];
    const float* wp1_b      = (const float*)d_in[19];
    const float* wp2_b      = (const float*)d_in[20];
    float* out = (float*)d_out;

    float *p_embT, *w_embT, *woutsT, *wmidT, *preT_p, *preT_w0;
    cudaGetSymbolAddress((void**)&p_embT, g_p_embT);
    cudaGetSymbolAddress((void**)&w_embT, g_w_embT);
    cudaGetSymbolAddress((void**)&woutsT, g_woutsT);
    cudaGetSymbolAddress((void**)&wmidT, g_wmidT);
    cudaGetSymbolAddress((void**)&preT_p, g_preT_p);
    cudaGetSymbolAddress((void**)&preT_w0, g_preT_w0);

    zero_init_kernel<<<(WORD_H * BB + 255) / 256, 256>>>();
    gather_kernel<<<(WORD_E * NTOK + 255) / 256, 256>>>(pos, word, pos_emb_W, word_emb_W);

    {
        const int total = 4 * POS_H * 1280 + 4 * WORD_H * 1280 + 4 * WORD_H * 2048 +
                          4 * POS_H + 2 * (4 * WORD_H);
        repack_kernel<<<(total + 255) / 256, 256>>>(
            pos_Wih, pos_Whh, w0_Wih, w0_Whh, w1_Wih, w1_Whh,
            pos_bih, pos_bhh, w0_bih, w0_bhh, w1_bih, w1_bhh);
    }

    // precompute emb @ Wih_emb-part for all timesteps (transposed outputs)
    gemm_t_kernel<<<dim3(4 * POS_H / 128, NTOK / 128), 256>>>(
        p_embT, NTOK, NTOK, pos_Wih, POS_E + WORD_H, nullptr,
        nullptr, preT_p, 4 * POS_H, POS_E);
    gemm_t_kernel<<<dim3(4 * WORD_H / 128, NTOK / 128), 256>>>(
        w_embT, NTOK, NTOK, w0_Wih, WORD_E + POS_H, nullptr,
        nullptr, preT_w0, 4 * WORD_H, WORD_E);

    // the whole 128-step recurrence in ONE persistent kernel
    recurrence_kernel<<<128, 256>>>();

    // pos projection + log-softmax
    pos_projT_kernel<<<TT, 256>>>(pos_proj_W, pos_proj_b, out);

    // word head
    gemm_t_kernel<<<dim3(WORD_E / 128, NTOK / 128), 256>>>(
        woutsT + 32, NTOK, NTOKP, wp1_W, WORD_H, wp1_b,
        nullptr, wmidT, WORD_E, WORD_H);
    float* wlp = out + (size_t)NTOK * POS_V;
    gemm_t_kernel<<<dim3(WORD_V / 128, NTOK / 128), 256>>>(
        wmidT, NTOK, NTOK, word_emb_W, WORD_E, wp2_b,
        wlp, nullptr, WORD_V, WORD_E);
    word_softmax_kernel<<<NTOK, 256>>>(wlp);
}

// round 6
// speedup vs baseline: 2.3023x; 1.1016x over previous
#include <cuda_runtime.h>
#include <math.h>

typedef unsigned long long ull;

// ---------------------------------------------------------------------------
// Problem constants
// ---------------------------------------------------------------------------
namespace {
constexpr int TT = 128, BB = 32;
constexpr int POS_E = 64, WORD_E = 512, POS_H = 256, WORD_H = 1024;
constexpr int POS_V = 45, WORD_V = 32000;
constexpr int NTOK = TT * BB;      // 4096
constexpr int NTOKP = NTOK + 32;   // history col 0 = zeros (t = -1 slot)

// ---------------------------------------------------------------------------
// Device scratch (static globals; no allocation allowed)
// ---------------------------------------------------------------------------
__device__ float g_p_embT[POS_E * NTOK];             // [E][tok]
__device__ float g_w_embT[WORD_E * NTOK];
__device__ float g_poutsT[POS_H * NTOKP];            // histories [H][NTOKP], slot t+1
__device__ float g_wh0T[WORD_H * NTOKP];
__device__ float g_woutsT[WORD_H * NTOKP];
__device__ float g_wmidT[WORD_E * NTOK];
__device__ float g_preT_p[4 * POS_H * NTOK];         // emb@Wih pos, [4H][tok]
__device__ float g_preT_w0[4 * WORD_H * NTOK];
// packed sequential weights, k-major per block: [blk][K][ROWS]
__device__ float g_Wpos[4 * POS_H * 1280];           // [128][1280][8]
__device__ float g_Ww0[4 * WORD_H * 1280];           // [128][1280][32]
__device__ float g_Ww1[4 * WORD_H * 2048];           // [128][2048][32]
__device__ float g_bpos[4 * POS_H], g_bw0[4 * WORD_H], g_bw1[4 * WORD_H];
// cell state ping-pong (each [H][32]; block-private rows)
__device__ float g_Cpos[2][POS_H * BB];
__device__ float g_Cw0[2][WORD_H * BB];
__device__ float g_Cw1[2][WORD_H * BB];
__device__ unsigned g_bar_ctr;
}  // namespace

// ---------------------------------------------------------------------------
// f32x2 packed helpers
// ---------------------------------------------------------------------------
__device__ __forceinline__ ull pack2(float lo, float hi) {
    ull r; asm("mov.b64 %0, {%1,%2};" : "=l"(r) : "f"(lo), "f"(hi)); return r;
}
__device__ __forceinline__ ull dup2(float v) { return pack2(v, v); }
__device__ __forceinline__ void fma2(ull& d, ull a, ull b) {
    asm("fma.rn.f32x2 %0, %1, %2, %0;" : "+l"(d) : "l"(a), "l"(b));
}
__device__ __forceinline__ void unpack2(ull v, float& lo, float& hi) {
    asm("mov.b64 {%0,%1}, %2;" : "=f"(lo), "=f"(hi) : "l"(v));
}
__device__ __forceinline__ float sigm(float x) { return 1.f / (1.f + expf(-x)); }

// ---------------------------------------------------------------------------
// Init / gather / weight repack
// ---------------------------------------------------------------------------
__global__ void zero_init_kernel() {
    int i = blockIdx.x * blockDim.x + threadIdx.x;
    if (i < POS_H * BB) {
        g_poutsT[(size_t)(i >> 5) * NTOKP + (i & 31)] = 0.f;
        g_Cpos[0][i] = 0.f;
    }
    if (i < WORD_H * BB) {
        int r = i >> 5, b = i & 31;
        g_wh0T[(size_t)r * NTOKP + b] = 0.f;
        g_woutsT[(size_t)r * NTOKP + b] = 0.f;
        g_Cw0[0][i] = 0.f;
        g_Cw1[0][i] = 0.f;
    }
    if (i == 0) g_bar_ctr = 0u;
}

__global__ void gather_kernel(const int* __restrict__ pos, const int* __restrict__ word,
                              const float* __restrict__ posW, const float* __restrict__ wordW) {
    int j = blockIdx.x * blockDim.x + threadIdx.x;
    if (j < WORD_E * NTOK) {
        int d = j / NTOK, tok = j - d * NTOK;
        g_w_embT[j] = wordW[(size_t)word[tok] * WORD_E + d];
    }
    if (j < POS_E * NTOK) {
        int d = j / NTOK, tok = j - d * NTOK;
        g_p_embT[j] = posW[(size_t)pos[tok] * POS_E + d];
    }
}

// Repack into k-major per-block layout (source row strides: 1088 / 768 / 1024).
__global__ void repack_kernel(const float* __restrict__ pWih, const float* __restrict__ pWhh,
                              const float* __restrict__ w0Wih, const float* __restrict__ w0Whh,
                              const float* __restrict__ w1Wih, const float* __restrict__ w1Whh,
                              const float* __restrict__ pbih, const float* __restrict__ pbhh,
                              const float* __restrict__ w0bih, const float* __restrict__ w0bhh,
                              const float* __restrict__ w1bih, const float* __restrict__ w1bhh) {
    int i = blockIdx.x * blockDim.x + threadIdx.x;
    const int A = 4 * POS_H * 1280;
    const int Bq = 4 * WORD_H * 1280;
    const int Cq = 4 * WORD_H * 2048;
    if (i < A) {
        int blk = i / (1280 * 8), rem = i - blk * (1280 * 8);
        int k = rem >> 3, rowl = rem & 7;
        int g = rowl >> 1, hh = rowl & 1;
        int R = g * POS_H + blk * 2 + hh;
        g_Wpos[i] = (k < 1024) ? pWih[(size_t)R * 1088 + 64 + k]
                               : pWhh[(size_t)R * 256 + (k - 1024)];
        return;
    }
    i -= A;
    if (i < Bq) {
        int blk = i / (1280 * 32), rem = i - blk * (1280 * 32);
        int k = rem >> 5, rowl = rem & 31;
        int g = rowl >> 3, hh = rowl & 7;
        int R = g * WORD_H + blk * 8 + hh;
        g_Ww0[i] = (k < 256) ? w0Wih[(size_t)R * 768 + 512 + k]
                             : w0Whh[(size_t)R * 1024 + (k - 256)];
        return;
    }
    i -= Bq;
    if (i < Cq) {
        int blk = i / (2048 * 32), rem = i - blk * (2048 * 32);
        int k = rem >> 5, rowl = rem & 31;
        int g = rowl >> 3, hh = rowl & 7;
        int R = g * WORD_H + blk * 8 + hh;
        g_Ww1[i] = (k < 1024) ? w1Wih[(size_t)R * 1024 + k]
                              : w1Whh[(size_t)R * 1024 + (k - 1024)];
        return;
    }
    i -= Cq;
    if (i < 4 * POS_H) { g_bpos[i] = pbih[i] + pbhh[i]; return; }
    i -= 4 * POS_H;
    if (i < 4 * WORD_H) { g_bw0[i] = w0bih[i] + w0bhh[i]; return; }
    i -= 4 * WORD_H;
    if (i < 4 * WORD_H) { g_bw1[i] = w1bih[i] + w1bhh[i]; }
}

// ---------------------------------------------------------------------------
// Persistent recurrence kernel: 128 blocks x 512 threads, 96KB dynamic smem.
// Layout: xs[128][32] | ws[128][32] | red[16][32][32]
// ---------------------------------------------------------------------------
constexpr int REC_THREADS = 512;
constexpr int REC_SMEM = (128 * 32 + 128 * 32 + 16 * 32 * 32) * 4;  // 98304

__device__ __forceinline__ void grid_barrier(unsigned target) {
    __syncthreads();
    if (threadIdx.x == 0) {
        __threadfence();
        atomicAdd(&g_bar_ctr, 1u);
        while (*(volatile unsigned*)&g_bar_ctr < target) __nanosleep(64);
        __threadfence();
    }
    __syncthreads();
}

// Word-size LSTM cell (H=1024). 128-k chunks; 16 warps = 16 k-slices (8 k each).
// Lane: rowg(8 groups of 4 rows) x bg(4 groups of 8 batch).
template <int K>
__device__ __forceinline__ void cell_word(
    float (*xs)[32], float (*ws)[32], float (*red)[32][32],
    const float* __restrict__ Wblk, const float* __restrict__ bcomb,
    const float* __restrict__ preT, int tok0,
    const float* __restrict__ x1, int K1, const float* __restrict__ x2,
    const float* __restrict__ cin, float* __restrict__ cout,
    float* __restrict__ hcol) {
    constexpr int NC = K / 128;
    const int tid = threadIdx.x;
    const int w = tid >> 5, lane = tid & 31;
    const int rowg = lane >> 2;   // rows rowg*4..+3
    const int bg = lane & 3;      // batch bg*8..+7

    ull acc[4][4];
#pragma unroll
    for (int r = 0; r < 4; r++)
#pragma unroll
        for (int j = 0; j < 4; j++) acc[r][j] = 0ull;

    float4 px[2], pw[2];
#pragma unroll
    for (int it = 0; it < 2; it++) {   // prefetch chunk 0 (always inside x1)
        int f = tid + it * REC_THREADS;
        px[it] = *(const float4*)(x1 + (size_t)(f >> 3) * NTOKP + (f & 7) * 4);
        pw[it] = *(const float4*)(Wblk + (size_t)(f >> 3) * 32 + (f & 7) * 4);
    }

    for (int c = 0; c < NC; c++) {
        __syncthreads();
#pragma unroll
        for (int it = 0; it < 2; it++) {
            int f = tid + it * REC_THREADS;
            *(float4*)&xs[f >> 3][(f & 7) * 4] = px[it];
            *(float4*)&ws[f >> 3][(f & 7) * 4] = pw[it];
        }
        __syncthreads();
        if (c + 1 < NC) {
            int kb = (c + 1) * 128;   // chunk boundaries align with K1 (256/1024)
            const float* xsrc = (kb < K1) ? x1 + (size_t)kb * NTOKP
                                          : x2 + (size_t)(kb - K1) * NTOKP;
            const float* wsrc = Wblk + (size_t)kb * 32;
#pragma unroll
            for (int it = 0; it < 2; it++) {
                int f = tid + it * REC_THREADS;
                px[it] = *(const float4*)(xsrc + (size_t)(f >> 3) * NTOKP + (f & 7) * 4);
                pw[it] = *(const float4*)(wsrc + (size_t)(f >> 3) * 32 + (f & 7) * 4);
            }
        }
#pragma unroll
        for (int kk = 0; kk < 8; kk++) {
            int k = w * 8 + kk;
            const ulonglong2* xp = (const ulonglong2*)&xs[k][bg * 8];
            ulonglong2 xv0 = xp[0], xv1 = xp[1];
            const float* wr = &ws[k][rowg * 4];
#pragma unroll
            for (int r = 0; r < 4; r++) {
                ull wd = dup2(wr[r]);
                fma2(acc[r][0], wd, xv0.x);
                fma2(acc[r][1], wd, xv0.y);
                fma2(acc[r][2], wd, xv1.x);
                fma2(acc[r][3], wd, xv1.y);
            }
        }
    }
    // dump k-slice partials
#pragma unroll
    for (int r = 0; r < 4; r++) {
        int row = rowg * 4 + r;
#pragma unroll
        for (int j = 0; j < 4; j += 2) {
            float a0, a1, a2, a3;
            unpack2(acc[r][j], a0, a1);
            unpack2(acc[r][j + 1], a2, a3);
            *(float4*)&red[w][row][bg * 8 + j * 2] = make_float4(a0, a1, a2, a3);
        }
    }
    __syncthreads();
    // gate stage: 256 threads = 8 h x 32 b
    if (tid < 256) {
        int hh = tid >> 5, b = tid & 31;
        int habs = blockIdx.x * 8 + hh;
        float gs[4];
#pragma unroll
        for (int g = 0; g < 4; g++) {
            float s = bcomb[g * WORD_H + habs];
#pragma unroll
            for (int ww = 0; ww < 16; ww++) s += red[ww][g * 8 + hh][b];
            if (preT) s += preT[(size_t)(g * WORD_H + habs) * NTOK + tok0 + b];
            gs[g] = s;
        }
        float i = sigm(gs[0]), f = sigm(gs[1]), g = tanhf(gs[2]), o = sigm(gs[3]);
        float c2 = f * cin[habs * 32 + b] + i * g;
        float h2 = o * tanhf(c2);
        cout[habs * 32 + b] = c2;
        hcol[(size_t)habs * NTOKP + b] = h2;
    }
}

// Pos cell (H=256, ROWS=8, K=1280, K1=1024). 128-k chunks; 8 k-slices of 64
// threads (16 k each). sub: rowl(8) x bg(8 groups of 4 batch).
__device__ __forceinline__ void cell_pos(
    float (*xs)[32], float (*ws)[32], float (*red)[32][32],
    const float* __restrict__ Wblk, const float* __restrict__ bcomb,
    const float* __restrict__ preT, int tok0,
    const float* __restrict__ x1 /*1024 rows*/, const float* __restrict__ x2 /*256*/,
    const float* __restrict__ cin, float* __restrict__ cout,
    float* __restrict__ hcol) {
    constexpr int K = 1280, NC = K / 128, K1 = 1024;
    const int tid = threadIdx.x;
    const int ksl = tid >> 6;     // 0..7
    const int sub = tid & 63;
    const int rowl = sub >> 3;    // 0..7
    const int bg = sub & 7;       // batch bg*4..+3

    ull acc0 = 0ull, acc1 = 0ull;
    float4 px[2], pw;
#pragma unroll
    for (int it = 0; it < 2; it++) {
        int f = tid + it * REC_THREADS;
        px[it] = *(const float4*)(x1 + (size_t)(f >> 3) * NTOKP + (f & 7) * 4);
    }
    if (tid < 256)
        pw = *(const float4*)(Wblk + (size_t)(tid >> 1) * 8 + (tid & 1) * 4);

    for (int c = 0; c < NC; c++) {
        __syncthreads();
#pragma unroll
        for (int it = 0; it < 2; it++) {
            int f = tid + it * REC_THREADS;
            *(float4*)&xs[f >> 3][(f & 7) * 4] = px[it];
        }
        if (tid < 256)
            *(float4*)&ws[tid >> 1][(tid & 1) * 4] = pw;
        __syncthreads();
        if (c + 1 < NC) {
            int kb = (c + 1) * 128;
            const float* xsrc = (kb < K1) ? x1 + (size_t)kb * NTOKP
                                          : x2 + (size_t)(kb - K1) * NTOKP;
#pragma unroll
            for (int it = 0; it < 2; it++) {
                int f = tid + it * REC_THREADS;
                px[it] = *(const float4*)(xsrc + (size_t)(f >> 3) * NTOKP + (f & 7) * 4);
            }
            if (tid < 256)
                pw = *(const float4*)(Wblk + (size_t)(kb + (tid >> 1)) * 8 + (tid & 1) * 4);
        }
#pragma unroll
        for (int kk = 0; kk < 16; kk++) {
            int k = ksl * 16 + kk;
            ulonglong2 xv = *(const ulonglong2*)&xs[k][bg * 4];
            ull wd = dup2(ws[k][rowl]);
            fma2(acc0, wd, xv.x);
            fma2(acc1, wd, xv.y);
        }
    }
    {
        float a0, a1, a2, a3;
        unpack2(acc0, a0, a1);
        unpack2(acc1, a2, a3);
        *(float4*)&red[ksl][rowl][bg * 4] = make_float4(a0, a1, a2, a3);
    }
    __syncthreads();
    if (tid < 64) {
        int hh = tid >> 5, b = tid & 31;
        int habs = blockIdx.x * 2 + hh;
        float gs[4];
#pragma unroll
        for (int g = 0; g < 4; g++) {
            float s = bcomb[g * POS_H + habs];
#pragma unroll
            for (int s8 = 0; s8 < 8; s8++) s += red[s8][g * 2 + hh][b];
            s += preT[(size_t)(g * POS_H + habs) * NTOK + tok0 + b];
            gs[g] = s;
        }
        float i = sigm(gs[0]), f = sigm(gs[1]), g = tanhf(gs[2]), o = sigm(gs[3]);
        float c2 = f * cin[habs * 32 + b] + i * g;
        float h2 = o * tanhf(c2);
        cout[habs * 32 + b] = c2;
        hcol[(size_t)habs * NTOKP + b] = h2;
    }
}

__global__ __launch_bounds__(REC_THREADS, 1) void recurrence_kernel() {
    extern __shared__ float smem[];
    float (*xs)[32] = (float(*)[32])smem;
    float (*ws)[32] = (float(*)[32])(smem + 128 * 32);
    float (*red)[32][32] = (float(*)[32][32])(smem + 2 * 128 * 32);
    unsigned ep = 0;
    const unsigned NB = gridDim.x;
    const int blk = blockIdx.x;
    const float* WposB = g_Wpos + (size_t)blk * 1280 * 8;
    const float* Ww0B  = g_Ww0 + (size_t)blk * 1280 * 32;
    const float* Ww1B  = g_Ww1 + (size_t)blk * 2048 * 32;
    for (int t = 0; t < TT; t++) {
        const int p = t & 1, q = p ^ 1;
        const int tok0 = t * BB;
        // pos: x = [w1_h(t-1); p_h(t-1)]
        cell_pos(xs, ws, red, WposB, g_bpos, g_preT_p, tok0,
                 g_woutsT + (size_t)t * 32, g_poutsT + (size_t)t * 32,
                 g_Cpos[p], g_Cpos[q], g_poutsT + (size_t)(t + 1) * 32);
        grid_barrier(++ep * NB);
        // w0: x = [p_h(t); wh0(t-1)]
        cell_word<1280>(xs, ws, red, Ww0B, g_bw0, g_preT_w0, tok0,
                        g_poutsT + (size_t)(t + 1) * 32, 256,
                        g_wh0T + (size_t)t * 32,
                        g_Cw0[p], g_Cw0[q], g_wh0T + (size_t)(t + 1) * 32);
        grid_barrier(++ep * NB);
        // w1: x = [wh0(t); w1_h(t-1)]
        cell_word<2048>(xs, ws, red, Ww1B, g_bw1, nullptr, tok0,
                        g_wh0T + (size_t)(t + 1) * 32, 1024,
                        g_woutsT + (size_t)t * 32,
                        g_Cw1[p], g_Cw1[q], g_woutsT + (size_t)(t + 1) * 32);
        grid_barrier(++ep * NB);
    }
}

// ---------------------------------------------------------------------------
// f32x2 GEMM: C[m,n] = sum_k AT[k,m]*W[n,k] + bias[n]; AT row stride = lda.
// ---------------------------------------------------------------------------
__global__ __launch_bounds__(256, 2) void gemm_t_kernel(
    const float* __restrict__ AT, int M, int lda,
    const float* __restrict__ W, int ldw, const float* __restrict__ bias,
    float* __restrict__ C, float* __restrict__ CT, int N, int K) {
    __shared__ float As[32][128];
    __shared__ float Ws[32][132];
    const int tid = threadIdx.x;
    const int rt = tid & 15;
    const int ct = tid >> 4;
    const int rBase = blockIdx.y * 128, cBase = blockIdx.x * 128;

    ull acc[8][4];
#pragma unroll
    for (int jj = 0; jj < 8; jj++)
#pragma unroll
        for (int p = 0; p < 4; p++) acc[jj][p] = 0ull;

    for (int kb = 0; kb < K; kb += 32) {
#pragma unroll
        for (int it = 0; it < 4; it++) {
            int flat = tid + it * 256;
            int k = flat >> 5, m4 = flat & 31;
            float4 v = *(const float4*)&AT[(size_t)(kb + k) * lda + rBase + m4 * 4];
            *(float4*)&As[k][m4 * 4] = v;
        }
#pragma unroll
        for (int it = 0; it < 4; it++) {
            int flat = tid + it * 256;
            int n = flat >> 3, k4 = flat & 7;
            float4 v = *(const float4*)&W[(size_t)(cBase + n) * ldw + kb + k4 * 4];
            Ws[k4 * 4 + 0][n] = v.x;
            Ws[k4 * 4 + 1][n] = v.y;
            Ws[k4 * 4 + 2][n] = v.z;
            Ws[k4 * 4 + 3][n] = v.w;
        }
        __syncthreads();
#pragma unroll
        for (int k = 0; k < 32; k++) {
            ull xd[8];
#pragma unroll
            for (int jj = 0; jj < 8; jj++) xd[jj] = dup2(As[k][rt + 16 * jj]);
            const ulonglong2* wpp = (const ulonglong2*)&Ws[k][ct * 8];
            ulonglong2 wa = wpp[0];
            ulonglong2 wb = wpp[1];
#pragma unroll
            for (int jj = 0; jj < 8; jj++) {
                fma2(acc[jj][0], xd[jj], wa.x);
                fma2(acc[jj][1], xd[jj], wa.y);
                fma2(acc[jj][2], xd[jj], wb.x);
                fma2(acc[jj][3], xd[jj], wb.y);
            }
        }
        __syncthreads();
    }
    float bcol[8];
#pragma unroll
    for (int qq = 0; qq < 8; qq++) bcol[qq] = bias ? bias[cBase + ct * 8 + qq] : 0.f;
#pragma unroll
    for (int jj = 0; jj < 8; jj++) {
        int m = rBase + rt + 16 * jj;
        float v[8];
#pragma unroll
        for (int p = 0; p < 4; p++) unpack2(acc[jj][p], v[2 * p], v[2 * p + 1]);
#pragma unroll
        for (int qq = 0; qq < 8; qq++) v[qq] += bcol[qq];
        if (C) {
            float4* dst = (float4*)&C[(size_t)m * N + cBase + ct * 8];
            dst[0] = make_float4(v[0], v[1], v[2], v[3]);
            dst[1] = make_float4(v[4], v[5], v[6], v[7]);
        }
        if (CT) {
#pragma unroll
            for (int qq = 0; qq < 8; qq++)
                CT[(size_t)(cBase + ct * 8 + qq) * M + m] = v[qq];
        }
    }
}

// ---------------------------------------------------------------------------
// pos projection + log-softmax (one block per timestep)
// ---------------------------------------------------------------------------
__global__ void pos_projT_kernel(const float* __restrict__ Wp, const float* __restrict__ bp,
                                 float* __restrict__ out) {
    __shared__ float xs[POS_H][32];
    __shared__ float lg[POS_V][33];
    __shared__ float lsb[32];
    const int t = blockIdx.x;
    const int tok0 = t * 32;
    const int tid = threadIdx.x;
    const int b = tid & 31, vg = tid >> 5;
    for (int i = tid; i < POS_H * 32; i += 256) {
        int k = i >> 5, bb = i & 31;
        xs[k][bb] = g_poutsT[(size_t)k * NTOKP + 32 + tok0 + bb];
    }
    __syncthreads();
    for (int v = vg; v < POS_V; v += 8) {
        float s = bp[v];
        const float* wv = Wp + (size_t)v * POS_H;
        for (int k = 0; k < POS_H; k++) s = fmaf(xs[k][b], wv[k], s);
        lg[v][b] = s;
    }
    __syncthreads();
    if (tid < 32) {
        float m = -INFINITY;
        for (int v = 0; v < POS_V; v++) m = fmaxf(m, lg[v][tid]);
        float e = 0.f;
        for (int v = 0; v < POS_V; v++) e += expf(lg[v][tid] - m);
        lsb[tid] = m + logf(e);
    }
    __syncthreads();
    float ls = lsb[b];
    for (int v = vg; v < POS_V; v += 8)
        out[(size_t)(tok0 + b) * POS_V + v] = lg[v][b] - ls;
}

// ---------------------------------------------------------------------------
// word log-softmax in place over 32000 (one block per row, float4)
// ---------------------------------------------------------------------------
__global__ void word_softmax_kernel(float* __restrict__ logits) {
    __shared__ float red[8];
    const int row = blockIdx.x;
    float4* p4 = (float4*)(logits + (size_t)row * WORD_V);
    const int NV4 = WORD_V / 4;  // 8000
    const int tid = threadIdx.x;  // 256
    float m = -INFINITY;
    for (int i = tid; i < NV4; i += 256) {
        float4 v = p4[i];
        m = fmaxf(m, fmaxf(fmaxf(v.x, v.y), fmaxf(v.z, v.w)));
    }
#pragma unroll
    for (int o = 16; o; o >>= 1) m = fmaxf(m, __shfl_xor_sync(0xffffffffu, m, o));
    if ((tid & 31) == 0) red[tid >> 5] = m;
    __syncthreads();
    float M = red[0];
#pragma unroll
    for (int w = 1; w < 8; w++) M = fmaxf(M, red[w]);
    __syncthreads();
    float s = 0.f;
    for (int i = tid; i < NV4; i += 256) {
        float4 v = p4[i];
        s += expf(v.x - M) + expf(v.y - M) + expf(v.z - M) + expf(v.w - M);
    }
#pragma unroll
    for (int o = 16; o; o >>= 1) s += __shfl_xor_sync(0xffffffffu, s, o);
    if ((tid & 31) == 0) red[tid >> 5] = s;
    __syncthreads();
    float S = 0.f;
#pragma unroll
    for (int w = 0; w < 8; w++) S += red[w];
    float ls = M + logf(S);
    for (int i = tid; i < NV4; i += 256) {
        float4 v = p4[i];
        v.x -= ls; v.y -= ls; v.z -= ls; v.w -= ls;
        p4[i] = v;
    }
}

// ---------------------------------------------------------------------------
// Host side
// ---------------------------------------------------------------------------
extern "C" void kernel_launch(void* const* d_in, const int* in_sizes, int n_in,
                              void* d_out, int out_size) {
    (void)in_sizes; (void)n_in; (void)out_size;
    const int*   pos        = (const int*)d_in[0];
    const int*   word       = (const int*)d_in[1];
    const float* pos_emb_W  = (const float*)d_in[2];
    const float* word_emb_W = (const float*)d_in[3];
    const float* pos_Wih    = (const float*)d_in[4];
    const float* pos_Whh    = (const float*)d_in[5];
    const float* pos_bih    = (const float*)d_in[6];
    const float* pos_bhh    = (const float*)d_in[7];
    const float* w0_Wih     = (const float*)d_in[8];
    const float* w0_Whh     = (const float*)d_in[9];
    const float* w0_bih     = (const float*)d_in[10];
    const float* w0_bhh     = (const float*)d_in[11];
    const float* w1_Wih     = (const float*)d_in[12];
    const float* w1_Whh     = (const float*)d_in[13];
    const float* w1_bih     = (const float*)d_in[14];
    const float* w1_bhh     = (const float*)d_in[15];
    const float* pos_proj_W = (const float*)d_in[16];
    const float* pos_proj_b = (const float*)d_in[17];
    const float* wp1_W      = (const float*)d_in[18];
    const float* wp1_b      = (const float*)d_in[19];
    const float* wp2_b      = (const float*)d_in[20];
    float* out = (float*)d_out;

    float *p_embT, *w_embT, *woutsT, *wmidT, *preT_p, *preT_w0;
    cudaGetSymbolAddress((void**)&p_embT, g_p_embT);
    cudaGetSymbolAddress((void**)&w_embT, g_w_embT);
    cudaGetSymbolAddress((void**)&woutsT, g_woutsT);
    cudaGetSymbolAddress((void**)&wmidT, g_wmidT);
    cudaGetSymbolAddress((void**)&preT_p, g_preT_p);
    cudaGetSymbolAddress((void**)&preT_w0, g_preT_w0);

    static bool attr_done = false;
    if (!attr_done) {
        cudaFuncSetAttribute(recurrence_kernel,
                             cudaFuncAttributeMaxDynamicSharedMemorySize, REC_SMEM);
        attr_done = true;
    }

    zero_init_kernel<<<(WORD_H * BB + 255) / 256, 256>>>();
    gather_kernel<<<(WORD_E * NTOK + 255) / 256, 256>>>(pos, word, pos_emb_W, word_emb_W);

    {
        const int total = 4 * POS_H * 1280 + 4 * WORD_H * 1280 + 4 * WORD_H * 2048 +
                          4 * POS_H + 2 * (4 * WORD_H);
        repack_kernel<<<(total + 255) / 256, 256>>>(
            pos_Wih, pos_Whh, w0_Wih, w0_Whh, w1_Wih, w1_Whh,
            pos_bih, pos_bhh, w0_bih, w0_bhh, w1_bih, w1_bhh);
    }

    // precompute emb @ Wih_emb-part for all timesteps (transposed outputs)
    gemm_t_kernel<<<dim3(4 * POS_H / 128, NTOK / 128), 256>>>(
        p_embT, NTOK, NTOK, pos_Wih, POS_E + WORD_H, nullptr,
        nullptr, preT_p, 4 * POS_H, POS_E);
    gemm_t_kernel<<<dim3(4 * WORD_H / 128, NTOK / 128), 256>>>(
        w_embT, NTOK, NTOK, w0_Wih, WORD_E + POS_H, nullptr,
        nullptr, preT_w0, 4 * WORD_H, WORD_E);

    // the whole 128-step recurrence in ONE persistent kernel
    recurrence_kernel<<<128, REC_THREADS, REC_SMEM>>>();

    // pos projection + log-softmax
    pos_projT_kernel<<<TT, 256>>>(pos_proj_W, pos_proj_b, out);

    // word head
    gemm_t_kernel<<<dim3(WORD_E / 128, NTOK / 128), 256>>>(
        woutsT + 32, NTOK, NTOKP, wp1_W, WORD_H, wp1_b,
        nullptr, wmidT, WORD_E, WORD_H);
    float* wlp = out + (size_t)NTOK * POS_V;
    gemm_t_kernel<<<dim3(WORD_V / 128, NTOK / 128), 256>>>(
        wmidT, NTOK, NTOK, word_emb_W, WORD_E, wp2_b,
        wlp, nullptr, WORD_V, WORD_E);
    word_softmax_kernel<<<NTOK, 256>>>(wlp);
}

// round 7
// speedup vs baseline: 2.4565x; 1.0670x over previous
#include <cuda_runtime.h>
#include <math.h>

typedef unsigned long long ull;

// ---------------------------------------------------------------------------
// Problem constants
// ---------------------------------------------------------------------------
namespace {
constexpr int TT = 128, BB = 32;
constexpr int POS_E = 64, WORD_E = 512, POS_H = 256, WORD_H = 1024;
constexpr int POS_V = 45, WORD_V = 32000;
constexpr int NTOK = TT * BB;      // 4096
constexpr int NTOKP = NTOK + 32;   // history col 0 = zeros (t = -1 slot)

// ---------------------------------------------------------------------------
// Device scratch (static globals; no allocation allowed)
// ---------------------------------------------------------------------------
__device__ float g_p_embT[POS_E * NTOK];             // [E][tok]
__device__ float g_w_embT[WORD_E * NTOK];
__device__ float g_poutsT[POS_H * NTOKP];            // histories [H][NTOKP], slot t+1
__device__ float g_wh0T[WORD_H * NTOKP];
__device__ float g_woutsT[WORD_H * NTOKP];
__device__ float g_wmidT[WORD_E * NTOK];
__device__ float g_preT_p[4 * POS_H * NTOK];         // emb@Wih pos, [4H][tok]
__device__ float g_preT_w0[4 * WORD_H * NTOK];
// packed sequential weights, k-major per block: [blk][K][ROWS]
__device__ float g_Wpos[4 * POS_H * 1280];           // [128][1280][8]
__device__ float g_Ww0[4 * WORD_H * 1280];           // [128][1280][32]
__device__ float g_Ww1[4 * WORD_H * 2048];           // [128][2048][32]
__device__ float g_bpos[4 * POS_H], g_bw0[4 * WORD_H], g_bw1[4 * WORD_H];
// cell state ping-pong (each [H][32]; block-private rows)
__device__ float g_Cpos[2][POS_H * BB];
__device__ float g_Cw0[2][WORD_H * BB];
__device__ float g_Cw1[2][WORD_H * BB];
__device__ unsigned g_bar_ctr;
}  // namespace

// ---------------------------------------------------------------------------
// f32x2 packed helpers
// ---------------------------------------------------------------------------
__device__ __forceinline__ ull pack2(float lo, float hi) {
    ull r; asm("mov.b64 %0, {%1,%2};" : "=l"(r) : "f"(lo), "f"(hi)); return r;
}
__device__ __forceinline__ ull dup2(float v) { return pack2(v, v); }
__device__ __forceinline__ void fma2(ull& d, ull a, ull b) {
    asm("fma.rn.f32x2 %0, %1, %2, %0;" : "+l"(d) : "l"(a), "l"(b));
}
__device__ __forceinline__ void unpack2(ull v, float& lo, float& hi) {
    asm("mov.b64 {%0,%1}, %2;" : "=f"(lo), "=f"(hi) : "l"(v));
}
__device__ __forceinline__ float sigm(float x) { return 1.f / (1.f + expf(-x)); }

// ---------------------------------------------------------------------------
// Init / gather / weight repack
// ---------------------------------------------------------------------------
__global__ void zero_init_kernel() {
    int i = blockIdx.x * blockDim.x + threadIdx.x;
    if (i < POS_H * BB) {
        g_poutsT[(size_t)(i >> 5) * NTOKP + (i & 31)] = 0.f;
        g_Cpos[0][i] = 0.f;
    }
    if (i < WORD_H * BB) {
        int r = i >> 5, b = i & 31;
        g_wh0T[(size_t)r * NTOKP + b] = 0.f;
        g_woutsT[(size_t)r * NTOKP + b] = 0.f;
        g_Cw0[0][i] = 0.f;
        g_Cw1[0][i] = 0.f;
    }
    if (i == 0) g_bar_ctr = 0u;
}

__global__ void gather_kernel(const int* __restrict__ pos, const int* __restrict__ word,
                              const float* __restrict__ posW, const float* __restrict__ wordW) {
    int j = blockIdx.x * blockDim.x + threadIdx.x;
    if (j < WORD_E * NTOK) {
        int d = j / NTOK, tok = j - d * NTOK;
        g_w_embT[j] = wordW[(size_t)word[tok] * WORD_E + d];
    }
    if (j < POS_E * NTOK) {
        int d = j / NTOK, tok = j - d * NTOK;
        g_p_embT[j] = posW[(size_t)pos[tok] * POS_E + d];
    }
}

// Repack into k-major per-block layout (source row strides: 1088 / 768 / 1024).
__global__ void repack_kernel(const float* __restrict__ pWih, const float* __restrict__ pWhh,
                              const float* __restrict__ w0Wih, const float* __restrict__ w0Whh,
                              const float* __restrict__ w1Wih, const float* __restrict__ w1Whh,
                              const float* __restrict__ pbih, const float* __restrict__ pbhh,
                              const float* __restrict__ w0bih, const float* __restrict__ w0bhh,
                              const float* __restrict__ w1bih, const float* __restrict__ w1bhh) {
    int i = blockIdx.x * blockDim.x + threadIdx.x;
    const int A = 4 * POS_H * 1280;
    const int Bq = 4 * WORD_H * 1280;
    const int Cq = 4 * WORD_H * 2048;
    if (i < A) {
        int blk = i / (1280 * 8), rem = i - blk * (1280 * 8);
        int k = rem >> 3, rowl = rem & 7;
        int g = rowl >> 1, hh = rowl & 1;
        int R = g * POS_H + blk * 2 + hh;
        g_Wpos[i] = (k < 1024) ? pWih[(size_t)R * 1088 + 64 + k]
                               : pWhh[(size_t)R * 256 + (k - 1024)];
        return;
    }
    i -= A;
    if (i < Bq) {
        int blk = i / (1280 * 32), rem = i - blk * (1280 * 32);
        int k = rem >> 5, rowl = rem & 31;
        int g = rowl >> 3, hh = rowl & 7;
        int R = g * WORD_H + blk * 8 + hh;
        g_Ww0[i] = (k < 256) ? w0Wih[(size_t)R * 768 + 512 + k]
                             : w0Whh[(size_t)R * 1024 + (k - 256)];
        return;
    }
    i -= Bq;
    if (i < Cq) {
        int blk = i / (2048 * 32), rem = i - blk * (2048 * 32);
        int k = rem >> 5, rowl = rem & 31;
        int g = rowl >> 3, hh = rowl & 7;
        int R = g * WORD_H + blk * 8 + hh;
        g_Ww1[i] = (k < 1024) ? w1Wih[(size_t)R * 1024 + k]
                              : w1Whh[(size_t)R * 1024 + (k - 1024)];
        return;
    }
    i -= Cq;
    if (i < 4 * POS_H) { g_bpos[i] = pbih[i] + pbhh[i]; return; }
    i -= 4 * POS_H;
    if (i < 4 * WORD_H) { g_bw0[i] = w0bih[i] + w0bhh[i]; return; }
    i -= 4 * WORD_H;
    if (i < 4 * WORD_H) { g_bw1[i] = w1bih[i] + w1bhh[i]; }
}

// ---------------------------------------------------------------------------
// Persistent recurrence kernel: 128 blocks x 512 threads, 192KB dynamic smem.
// Layout: xs[2][256][32] | ws[2][256][32] | red[16][32][32]
// Double-buffered 256-k chunks: LDG(c+1) -> compute(c) -> STS(c+1) -> sync.
// ---------------------------------------------------------------------------
constexpr int REC_THREADS = 512;
constexpr int REC_SMEM = (2 * 256 * 32 + 2 * 256 * 32 + 16 * 32 * 32) * 4;  // 196608

__device__ __forceinline__ void grid_barrier(unsigned target) {
    __syncthreads();
    if (threadIdx.x == 0) {
        __threadfence();
        atomicAdd(&g_bar_ctr, 1u);
        while (*(volatile unsigned*)&g_bar_ctr < target) __nanosleep(64);
        __threadfence();
    }
    __syncthreads();
}

// Word-size LSTM cell (H=1024). 256-k chunks; 16 warps = 16 k-slices (16 k each).
// Lane: rowg(8 groups of 4 rows) x bg(4 groups of 8 batch).
template <int K>
__device__ __forceinline__ void cell_word(
    float (*xs)[256][32], float (*ws)[256][32], float (*red)[32][32],
    const float* __restrict__ Wblk, const float* __restrict__ bcomb,
    const float* __restrict__ preT, int tok0,
    const float* __restrict__ x1, int K1, const float* __restrict__ x2,
    const float* __restrict__ cin, float* __restrict__ cout,
    float* __restrict__ hcol) {
    constexpr int NC = K / 256;
    const int tid = threadIdx.x;
    const int w = tid >> 5, lane = tid & 31;
    const int rowg = lane >> 2;   // rows rowg*4..+3
    const int bg = lane & 3;      // batch bg*8..+7

    // gate-operand prefetch (hh = w for tid<256; gb = lane)
    const int hh = tid >> 5, gb = tid & 31;
    const int habs_g = blockIdx.x * 8 + hh;
    float cin_v = 0.f, bb[4], pre_g[4];
    if (tid < 256) {
        cin_v = cin[habs_g * 32 + gb];
#pragma unroll
        for (int g = 0; g < 4; g++) {
            bb[g] = bcomb[g * WORD_H + habs_g];
            pre_g[g] = preT ? preT[(size_t)(g * WORD_H + habs_g) * NTOK + tok0 + gb] : 0.f;
        }
    }

    ull acc[4][4];
#pragma unroll
    for (int r = 0; r < 4; r++)
#pragma unroll
        for (int j = 0; j < 4; j++) acc[r][j] = 0ull;

    float4 px[4], pw[4];
#pragma unroll
    for (int it = 0; it < 4; it++) {   // chunk 0 (always inside x1)
        int f = tid + it * REC_THREADS;
        px[it] = *(const float4*)(x1 + (size_t)(f >> 3) * NTOKP + (f & 7) * 4);
        pw[it] = *(const float4*)(Wblk + (size_t)(f >> 3) * 32 + (f & 7) * 4);
    }
#pragma unroll
    for (int it = 0; it < 4; it++) {
        int f = tid + it * REC_THREADS;
        *(float4*)&xs[0][f >> 3][(f & 7) * 4] = px[it];
        *(float4*)&ws[0][f >> 3][(f & 7) * 4] = pw[it];
    }
    __syncthreads();

    for (int c = 0; c < NC; c++) {
        const int cur = c & 1, nxt = cur ^ 1;
        if (c + 1 < NC) {   // issue loads for next chunk (overlap with compute)
            int kb = (c + 1) * 256;
            const float* xsrc = (kb < K1) ? x1 + (size_t)kb * NTOKP
                                          : x2 + (size_t)(kb - K1) * NTOKP;
            const float* wsrc = Wblk + (size_t)kb * 32;
#pragma unroll
            for (int it = 0; it < 4; it++) {
                int f = tid + it * REC_THREADS;
                px[it] = *(const float4*)(xsrc + (size_t)(f >> 3) * NTOKP + (f & 7) * 4);
                pw[it] = *(const float4*)(wsrc + (size_t)(f >> 3) * 32 + (f & 7) * 4);
            }
        }
#pragma unroll
        for (int kk = 0; kk < 16; kk++) {
            int k = w * 16 + kk;
            const ulonglong2* xp = (const ulonglong2*)&xs[cur][k][bg * 8];
            ulonglong2 xv0 = xp[0], xv1 = xp[1];
            float4 wv = *(const float4*)&ws[cur][k][rowg * 4];
            ull wd0 = dup2(wv.x), wd1 = dup2(wv.y), wd2 = dup2(wv.z), wd3 = dup2(wv.w);
            fma2(acc[0][0], wd0, xv0.x); fma2(acc[0][1], wd0, xv0.y);
            fma2(acc[0][2], wd0, xv1.x); fma2(acc[0][3], wd0, xv1.y);
            fma2(acc[1][0], wd1, xv0.x); fma2(acc[1][1], wd1, xv0.y);
            fma2(acc[1][2], wd1, xv1.x); fma2(acc[1][3], wd1, xv1.y);
            fma2(acc[2][0], wd2, xv0.x); fma2(acc[2][1], wd2, xv0.y);
            fma2(acc[2][2], wd2, xv1.x); fma2(acc[2][3], wd2, xv1.y);
            fma2(acc[3][0], wd3, xv0.x); fma2(acc[3][1], wd3, xv0.y);
            fma2(acc[3][2], wd3, xv1.x); fma2(acc[3][3], wd3, xv1.y);
        }
        if (c + 1 < NC) {
#pragma unroll
            for (int it = 0; it < 4; it++) {
                int f = tid + it * REC_THREADS;
                *(float4*)&xs[nxt][f >> 3][(f & 7) * 4] = px[it];
                *(float4*)&ws[nxt][f >> 3][(f & 7) * 4] = pw[it];
            }
        }
        __syncthreads();
    }
    // dump k-slice partials
#pragma unroll
    for (int r = 0; r < 4; r++) {
        int row = rowg * 4 + r;
#pragma unroll
        for (int j = 0; j < 4; j += 2) {
            float a0, a1, a2, a3;
            unpack2(acc[r][j], a0, a1);
            unpack2(acc[r][j + 1], a2, a3);
            *(float4*)&red[w][row][bg * 8 + j * 2] = make_float4(a0, a1, a2, a3);
        }
    }
    __syncthreads();
    // gate stage: 256 threads = 8 h x 32 b (operands prefetched)
    if (tid < 256) {
        float gs[4];
#pragma unroll
        for (int g = 0; g < 4; g++) {
            float s = bb[g] + pre_g[g];
#pragma unroll
            for (int ww = 0; ww < 16; ww++) s += red[ww][g * 8 + hh][gb];
            gs[g] = s;
        }
        float i = sigm(gs[0]), f = sigm(gs[1]), g = tanhf(gs[2]), o = sigm(gs[3]);
        float c2 = f * cin_v + i * g;
        float h2 = o * tanhf(c2);
        cout[habs_g * 32 + gb] = c2;
        hcol[(size_t)habs_g * NTOKP + gb] = h2;
    }
}

// Pos cell (H=256, ROWS=8, K=1280, K1=1024). 256-k chunks; 8 k-slices of 64
// threads (32 k each). sub: rowl(8) x bg(8 groups of 4 batch).
__device__ __forceinline__ void cell_pos(
    float (*xs)[256][32], float (*ws)[256][32], float (*red)[32][32],
    const float* __restrict__ Wblk, const float* __restrict__ bcomb,
    const float* __restrict__ preT, int tok0,
    const float* __restrict__ x1 /*1024 rows*/, const float* __restrict__ x2 /*256*/,
    const float* __restrict__ cin, float* __restrict__ cout,
    float* __restrict__ hcol) {
    constexpr int K = 1280, NC = K / 256, K1 = 1024;
    const int tid = threadIdx.x;
    const int ksl = tid >> 6;     // 0..7
    const int sub = tid & 63;
    const int rowl = sub >> 3;    // 0..7
    const int bg = sub & 7;       // batch bg*4..+3

    // gate-operand prefetch
    const int hh = tid >> 5, gb = tid & 31;
    const int habs_g = blockIdx.x * 2 + hh;
    float cin_v = 0.f, bb[4], pre_g[4];
    if (tid < 64) {
        cin_v = cin[habs_g * 32 + gb];
#pragma unroll
        for (int g = 0; g < 4; g++) {
            bb[g] = bcomb[g * POS_H + habs_g];
            pre_g[g] = preT[(size_t)(g * POS_H + habs_g) * NTOK + tok0 + gb];
        }
    }

    ull acc0 = 0ull, acc1 = 0ull;
    float4 px[4], pw;
#pragma unroll
    for (int it = 0; it < 4; it++) {
        int f = tid + it * REC_THREADS;
        px[it] = *(const float4*)(x1 + (size_t)(f >> 3) * NTOKP + (f & 7) * 4);
    }
    pw = *(const float4*)(Wblk + (size_t)(tid >> 1) * 8 + (tid & 1) * 4);
#pragma unroll
    for (int it = 0; it < 4; it++) {
        int f = tid + it * REC_THREADS;
        *(float4*)&xs[0][f >> 3][(f & 7) * 4] = px[it];
    }
    *(float4*)&ws[0][tid >> 1][(tid & 1) * 4] = pw;
    __syncthreads();

    for (int c = 0; c < NC; c++) {
        const int cur = c & 1, nxt = cur ^ 1;
        if (c + 1 < NC) {
            int kb = (c + 1) * 256;
            const float* xsrc = (kb < K1) ? x1 + (size_t)kb * NTOKP
                                          : x2 + (size_t)(kb - K1) * NTOKP;
#pragma unroll
            for (int it = 0; it < 4; it++) {
                int f = tid + it * REC_THREADS;
                px[it] = *(const float4*)(xsrc + (size_t)(f >> 3) * NTOKP + (f & 7) * 4);
            }
            pw = *(const float4*)(Wblk + (size_t)(kb + (tid >> 1)) * 8 + (tid & 1) * 4);
        }
#pragma unroll
        for (int kk = 0; kk < 32; kk++) {
            int k = ksl * 32 + kk;
            ulonglong2 xv = *(const ulonglong2*)&xs[cur][k][bg * 4];
            ull wd = dup2(ws[cur][k][rowl]);
            fma2(acc0, wd, xv.x);
            fma2(acc1, wd, xv.y);
        }
        if (c + 1 < NC) {
#pragma unroll
            for (int it = 0; it < 4; it++) {
                int f = tid + it * REC_THREADS;
                *(float4*)&xs[nxt][f >> 3][(f & 7) * 4] = px[it];
            }
            *(float4*)&ws[nxt][tid >> 1][(tid & 1) * 4] = pw;
        }
        __syncthreads();
    }
    {
        float a0, a1, a2, a3;
        unpack2(acc0, a0, a1);
        unpack2(acc1, a2, a3);
        *(float4*)&red[ksl][rowl][bg * 4] = make_float4(a0, a1, a2, a3);
    }
    __syncthreads();
    if (tid < 64) {
        float gs[4];
#pragma unroll
        for (int g = 0; g < 4; g++) {
            float s = bb[g] + pre_g[g];
#pragma unroll
            for (int s8 = 0; s8 < 8; s8++) s += red[s8][g * 2 + hh][gb];
            gs[g] = s;
        }
        float i = sigm(gs[0]), f = sigm(gs[1]), g = tanhf(gs[2]), o = sigm(gs[3]);
        float c2 = f * cin_v + i * g;
        float h2 = o * tanhf(c2);
        cout[habs_g * 32 + gb] = c2;
        hcol[(size_t)habs_g * NTOKP + gb] = h2;
    }
}

__global__ __launch_bounds__(REC_THREADS, 1) void recurrence_kernel() {
    extern __shared__ float smem[];
    float (*xs)[256][32] = (float(*)[256][32])smem;
    float (*ws)[256][32] = (float(*)[256][32])(smem + 2 * 256 * 32);
    float (*red)[32][32] = (float(*)[32][32])(smem + 4 * 256 * 32);
    unsigned ep = 0;
    const unsigned NB = gridDim.x;
    const int blk = blockIdx.x;
    const float* WposB = g_Wpos + (size_t)blk * 1280 * 8;
    const float* Ww0B  = g_Ww0 + (size_t)blk * 1280 * 32;
    const float* Ww1B  = g_Ww1 + (size_t)blk * 2048 * 32;
    for (int t = 0; t < TT; t++) {
        const int p = t & 1, q = p ^ 1;
        const int tok0 = t * BB;
        // pos: x = [w1_h(t-1); p_h(t-1)]
        cell_pos(xs, ws, red, WposB, g_bpos, g_preT_p, tok0,
                 g_woutsT + (size_t)t * 32, g_poutsT + (size_t)t * 32,
                 g_Cpos[p], g_Cpos[q], g_poutsT + (size_t)(t + 1) * 32);
        grid_barrier(++ep * NB);
        // w0: x = [p_h(t); wh0(t-1)]
        cell_word<1280>(xs, ws, red, Ww0B, g_bw0, g_preT_w0, tok0,
                        g_poutsT + (size_t)(t + 1) * 32, 256,
                        g_wh0T + (size_t)t * 32,
                        g_Cw0[p], g_Cw0[q], g_wh0T + (size_t)(t + 1) * 32);
        grid_barrier(++ep * NB);
        // w1: x = [wh0(t); w1_h(t-1)]
        cell_word<2048>(xs, ws, red, Ww1B, g_bw1, nullptr, tok0,
                        g_wh0T + (size_t)(t + 1) * 32, 1024,
                        g_woutsT + (size_t)t * 32,
                        g_Cw1[p], g_Cw1[q], g_woutsT + (size_t)(t + 1) * 32);
        grid_barrier(++ep * NB);
    }
}

// ---------------------------------------------------------------------------
// f32x2 GEMM: C[m,n] = sum_k AT[k,m]*W[n,k] + bias[n]; AT row stride = lda.
// ---------------------------------------------------------------------------
__global__ __launch_bounds__(256, 2) void gemm_t_kernel(
    const float* __restrict__ AT, int M, int lda,
    const float* __restrict__ W, int ldw, const float* __restrict__ bias,
    float* __restrict__ C, float* __restrict__ CT, int N, int K) {
    __shared__ float As[32][128];
    __shared__ float Ws[32][132];
    const int tid = threadIdx.x;
    const int rt = tid & 15;
    const int ct = tid >> 4;
    const int rBase = blockIdx.y * 128, cBase = blockIdx.x * 128;

    ull acc[8][4];
#pragma unroll
    for (int jj = 0; jj < 8; jj++)
#pragma unroll
        for (int p = 0; p < 4; p++) acc[jj][p] = 0ull;

    for (int kb = 0; kb < K; kb += 32) {
#pragma unroll
        for (int it = 0; it < 4; it++) {
            int flat = tid + it * 256;
            int k = flat >> 5, m4 = flat & 31;
            float4 v = *(const float4*)&AT[(size_t)(kb + k) * lda + rBase + m4 * 4];
            *(float4*)&As[k][m4 * 4] = v;
        }
#pragma unroll
        for (int it = 0; it < 4; it++) {
            int flat = tid + it * 256;
            int n = flat >> 3, k4 = flat & 7;
            float4 v = *(const float4*)&W[(size_t)(cBase + n) * ldw + kb + k4 * 4];
            Ws[k4 * 4 + 0][n] = v.x;
            Ws[k4 * 4 + 1][n] = v.y;
            Ws[k4 * 4 + 2][n] = v.z;
            Ws[k4 * 4 + 3][n] = v.w;
        }
        __syncthreads();
#pragma unroll
        for (int k = 0; k < 32; k++) {
            ull xd[8];
#pragma unroll
            for (int jj = 0; jj < 8; jj++) xd[jj] = dup2(As[k][rt + 16 * jj]);
            const ulonglong2* wpp = (const ulonglong2*)&Ws[k][ct * 8];
            ulonglong2 wa = wpp[0];
            ulonglong2 wb = wpp[1];
#pragma unroll
            for (int jj = 0; jj < 8; jj++) {
                fma2(acc[jj][0], xd[jj], wa.x);
                fma2(acc[jj][1], xd[jj], wa.y);
                fma2(acc[jj][2], xd[jj], wb.x);
                fma2(acc[jj][3], xd[jj], wb.y);
            }
        }
        __syncthreads();
    }
    float bcol[8];
#pragma unroll
    for (int qq = 0; qq < 8; qq++) bcol[qq] = bias ? bias[cBase + ct * 8 + qq] : 0.f;
#pragma unroll
    for (int jj = 0; jj < 8; jj++) {
        int m = rBase + rt + 16 * jj;
        float v[8];
#pragma unroll
        for (int p = 0; p < 4; p++) unpack2(acc[jj][p], v[2 * p], v[2 * p + 1]);
#pragma unroll
        for (int qq = 0; qq < 8; qq++) v[qq] += bcol[qq];
        if (C) {
            float4* dst = (float4*)&C[(size_t)m * N + cBase + ct * 8];
            dst[0] = make_float4(v[0], v[1], v[2], v[3]);
            dst[1] = make_float4(v[4], v[5], v[6], v[7]);
        }
        if (CT) {
#pragma unroll
            for (int qq = 0; qq < 8; qq++)
                CT[(size_t)(cBase + ct * 8 + qq) * M + m] = v[qq];
        }
    }
}

// ---------------------------------------------------------------------------
// pos projection + log-softmax (one block per timestep)
// ---------------------------------------------------------------------------
__global__ void pos_projT_kernel(const float* __restrict__ Wp, const float* __restrict__ bp,
                                 float* __restrict__ out) {
    __shared__ float xs[POS_H][32];
    __shared__ float lg[POS_V][33];
    __shared__ float lsb[32];
    const int t = blockIdx.x;
    const int tok0 = t * 32;
    const int tid = threadIdx.x;
    const int b = tid & 31, vg = tid >> 5;
    for (int i = tid; i < POS_H * 32; i += 256) {
        int k = i >> 5, bb = i & 31;
        xs[k][bb] = g_poutsT[(size_t)k * NTOKP + 32 + tok0 + bb];
    }
    __syncthreads();
    for (int v = vg; v < POS_V; v += 8) {
        float s = bp[v];
        const float* wv = Wp + (size_t)v * POS_H;
        for (int k = 0; k < POS_H; k++) s = fmaf(xs[k][b], wv[k], s);
        lg[v][b] = s;
    }
    __syncthreads();
    if (tid < 32) {
        float m = -INFINITY;
        for (int v = 0; v < POS_V; v++) m = fmaxf(m, lg[v][tid]);
        float e = 0.f;
        for (int v = 0; v < POS_V; v++) e += expf(lg[v][tid] - m);
        lsb[tid] = m + logf(e);
    }
    __syncthreads();
    float ls = lsb[b];
    for (int v = vg; v < POS_V; v += 8)
        out[(size_t)(tok0 + b) * POS_V + v] = lg[v][b] - ls;
}

// ---------------------------------------------------------------------------
// word log-softmax in place over 32000 (one block per row, float4)
// ---------------------------------------------------------------------------
__global__ void word_softmax_kernel(float* __restrict__ logits) {
    __shared__ float red[8];
    const int row = blockIdx.x;
    float4* p4 = (float4*)(logits + (size_t)row * WORD_V);
    const int NV4 = WORD_V / 4;  // 8000
    const int tid = threadIdx.x;  // 256
    float m = -INFINITY;
    for (int i = tid; i < NV4; i += 256) {
        float4 v = p4[i];
        m = fmaxf(m, fmaxf(fmaxf(v.x, v.y), fmaxf(v.z, v.w)));
    }
#pragma unroll
    for (int o = 16; o; o >>= 1) m = fmaxf(m, __shfl_xor_sync(0xffffffffu, m, o));
    if ((tid & 31) == 0) red[tid >> 5] = m;
    __syncthreads();
    float M = red[0];
#pragma unroll
    for (int w = 1; w < 8; w++) M = fmaxf(M, red[w]);
    __syncthreads();
    float s = 0.f;
    for (int i = tid; i < NV4; i += 256) {
        float4 v = p4[i];
        s += expf(v.x - M) + expf(v.y - M) + expf(v.z - M) + expf(v.w - M);
    }
#pragma unroll
    for (int o = 16; o; o >>= 1) s += __shfl_xor_sync(0xffffffffu, s, o);
    if ((tid & 31) == 0) red[tid >> 5] = s;
    __syncthreads();
    float S = 0.f;
#pragma unroll
    for (int w = 0; w < 8; w++) S += red[w];
    float ls = M + logf(S);
    for (int i = tid; i < NV4; i += 256) {
        float4 v = p4[i];
        v.x -= ls; v.y -= ls; v.z -= ls; v.w -= ls;
        p4[i] = v;
    }
}

// ---------------------------------------------------------------------------
// Host side
// ---------------------------------------------------------------------------
extern "C" void kernel_launch(void* const* d_in, const int* in_sizes, int n_in,
                              void* d_out, int out_size) {
    (void)in_sizes; (void)n_in; (void)out_size;
    const int*   pos        = (const int*)d_in[0];
    const int*   word       = (const int*)d_in[1];
    const float* pos_emb_W  = (const float*)d_in[2];
    const float* word_emb_W = (const float*)d_in[3];
    const float* pos_Wih    = (const float*)d_in[4];
    const float* pos_Whh    = (const float*)d_in[5];
    const float* pos_bih    = (const float*)d_in[6];
    const float* pos_bhh    = (const float*)d_in[7];
    const float* w0_Wih     = (const float*)d_in[8];
    const float* w0_Whh     = (const float*)d_in[9];
    const float* w0_bih     = (const float*)d_in[10];
    const float* w0_bhh     = (const float*)d_in[11];
    const float* w1_Wih     = (const float*)d_in[12];
    const float* w1_Whh     = (const float*)d_in[13];
    const float* w1_bih     = (const float*)d_in[14];
    const float* w1_bhh     = (const float*)d_in[15];
    const float* pos_proj_W = (const float*)d_in[16];
    const float* pos_proj_b = (const float*)d_in[17];
    const float* wp1_W      = (const float*)d_in[18];
    const float* wp1_b      = (const float*)d_in[19];
    const float* wp2_b      = (const float*)d_in[20];
    float* out = (float*)d_out;

    float *p_embT, *w_embT, *woutsT, *wmidT, *preT_p, *preT_w0;
    cudaGetSymbolAddress((void**)&p_embT, g_p_embT);
    cudaGetSymbolAddress((void**)&w_embT, g_w_embT);
    cudaGetSymbolAddress((void**)&woutsT, g_woutsT);
    cudaGetSymbolAddress((void**)&wmidT, g_wmidT);
    cudaGetSymbolAddress((void**)&preT_p, g_preT_p);
    cudaGetSymbolAddress((void**)&preT_w0, g_preT_w0);

    static bool attr_done = false;
    if (!attr_done) {
        cudaFuncSetAttribute(recurrence_kernel,
                             cudaFuncAttributeMaxDynamicSharedMemorySize, REC_SMEM);
        attr_done = true;
    }

    zero_init_kernel<<<(WORD_H * BB + 255) / 256, 256>>>();
    gather_kernel<<<(WORD_E * NTOK + 255) / 256, 256>>>(pos, word, pos_emb_W, word_emb_W);

    {
        const int total = 4 * POS_H * 1280 + 4 * WORD_H * 1280 + 4 * WORD_H * 2048 +
                          4 * POS_H + 2 * (4 * WORD_H);
        repack_kernel<<<(total + 255) / 256, 256>>>(
            pos_Wih, pos_Whh, w0_Wih, w0_Whh, w1_Wih, w1_Whh,
            pos_bih, pos_bhh, w0_bih, w0_bhh, w1_bih, w1_bhh);
    }

    // precompute emb @ Wih_emb-part for all timesteps (transposed outputs)
    gemm_t_kernel<<<dim3(4 * POS_H / 128, NTOK / 128), 256>>>(
        p_embT, NTOK, NTOK, pos_Wih, POS_E + WORD_H, nullptr,
        nullptr, preT_p, 4 * POS_H, POS_E);
    gemm_t_kernel<<<dim3(4 * WORD_H / 128, NTOK / 128), 256>>>(
        w_embT, NTOK, NTOK, w0_Wih, WORD_E + POS_H, nullptr,
        nullptr, preT_w0, 4 * WORD_H, WORD_E);

    // the whole 128-step recurrence in ONE persistent kernel
    recurrence_kernel<<<128, REC_THREADS, REC_SMEM>>>();

    // pos projection + log-softmax
    pos_projT_kernel<<<TT, 256>>>(pos_proj_W, pos_proj_b, out);

    // word head
    gemm_t_kernel<<<dim3(WORD_E / 128, NTOK / 128), 256>>>(
        woutsT + 32, NTOK, NTOKP, wp1_W, WORD_H, wp1_b,
        nullptr, wmidT, WORD_E, WORD_H);
    float* wlp = out + (size_t)NTOK * POS_V;
    gemm_t_kernel<<<dim3(WORD_V / 128, NTOK / 128), 256>>>(
        wmidT, NTOK, NTOK, word_emb_W, WORD_E, wp2_b,
        wlp, nullptr, WORD_V, WORD_E);
    word_softmax_kernel<<<NTOK, 256>>>(wlp);
}